// round 4
// baseline (speedup 1.0000x reference)
#include <cuda_runtime.h>

// Problem constants
#define B_DIM 16384
#define I_DIM 512
#define H1D   256
#define H2D   128
#define E_DIM 8
#define T_DIM 2

// Scratch (device globals: allocation-free per harness rules)
__device__ float g_h[(size_t)E_DIM * B_DIM * H1D];        // 134 MB: relu(x@W1+b1)
__device__ float g_gates[(size_t)T_DIM * B_DIM * E_DIM];  // 1 MB: softmaxed gates

// ---------------------------------------------------------------------------
// Kernel 1: per-task gate softmax.  One warp per row b.
// gates[t][b][e] = softmax_e( x[b]·Wg[t,:,e] + bg[t,e] )
// ---------------------------------------------------------------------------
__global__ void gates_kernel(const float* __restrict__ x,
                             const float* __restrict__ Wg,
                             const float* __restrict__ bg) {
    int warp = (blockIdx.x * blockDim.x + threadIdx.x) >> 5;
    int lane = threadIdx.x & 31;
    if (warp >= B_DIM) return;
    int b = warp;
    float acc[16];
#pragma unroll
    for (int j = 0; j < 16; j++) acc[j] = 0.f;

    const float* xr = x + (size_t)b * I_DIM;
#pragma unroll 4
    for (int ii = 0; ii < 16; ii++) {
        int i = ii * 32 + lane;
        float xv = xr[i];
#pragma unroll
        for (int t = 0; t < T_DIM; t++) {
            const float4* wp = (const float4*)(Wg + ((size_t)t * I_DIM + i) * E_DIM);
            float4 w0 = wp[0], w1 = wp[1];
            acc[t*8+0] += xv * w0.x; acc[t*8+1] += xv * w0.y;
            acc[t*8+2] += xv * w0.z; acc[t*8+3] += xv * w0.w;
            acc[t*8+4] += xv * w1.x; acc[t*8+5] += xv * w1.y;
            acc[t*8+6] += xv * w1.z; acc[t*8+7] += xv * w1.w;
        }
    }
#pragma unroll
    for (int j = 0; j < 16; j++) {
#pragma unroll
        for (int off = 16; off > 0; off >>= 1)
            acc[j] += __shfl_xor_sync(0xffffffffu, acc[j], off);
    }
    if (lane == 0) {
#pragma unroll
        for (int t = 0; t < T_DIM; t++) {
            float m = -1e30f;
#pragma unroll
            for (int e = 0; e < E_DIM; e++) {
                float v = acc[t*8+e] + bg[t*E_DIM + e];
                acc[t*8+e] = v;
                m = fmaxf(m, v);
            }
            float ex[E_DIM];
            float s = 0.f;
#pragma unroll
            for (int e = 0; e < E_DIM; e++) { ex[e] = expf(acc[t*8+e] - m); s += ex[e]; }
            float inv = 1.f / s;
#pragma unroll
            for (int e = 0; e < E_DIM; e++)
                g_gates[((size_t)t * B_DIM + b) * E_DIM + e] = ex[e] * inv;
        }
    }
}

// ---------------------------------------------------------------------------
// Kernel 2: h[e] = relu(x @ W1[e] + b1[e])   -> g_h [E, B, H1]
// Tiled GEMM: BM=BN=64, BK=16, 256 threads, 4x4 register micro-tile.
// grid = (B/64, H1/64, E)
// ---------------------------------------------------------------------------
__global__ void layer1_kernel(const float* __restrict__ x,
                              const float* __restrict__ W1,
                              const float* __restrict__ b1) {
    __shared__ float As[16][65];   // As[k][m], padded
    __shared__ float Bs[16][64];   // Bs[k][n]

    int e  = blockIdx.z;
    int n0 = blockIdx.y * 64;
    int m0 = blockIdx.x * 64;
    int tid = threadIdx.x;
    int ty = tid >> 4;        // 0..15  (rows ty*4 .. ty*4+3)
    int tx = tid & 15;        // 0..15  (cols tx*4 .. tx*4+3)

    float acc[4][4];
#pragma unroll
    for (int i = 0; i < 4; i++)
#pragma unroll
        for (int j = 0; j < 4; j++) acc[i][j] = 0.f;

    const float* W1e = W1 + (size_t)e * I_DIM * H1D;

    int lr = tid >> 2;           // A-load row 0..63
    int lc = (tid & 3) * 4;      // A-load k offset 0..12
    int wk = tid >> 4;           // B-load k row 0..15
    int wc = (tid & 15) * 4;     // B-load col offset

    for (int k0 = 0; k0 < I_DIM; k0 += 16) {
        float4 av = *(const float4*)(x + (size_t)(m0 + lr) * I_DIM + k0 + lc);
        As[lc + 0][lr] = av.x;
        As[lc + 1][lr] = av.y;
        As[lc + 2][lr] = av.z;
        As[lc + 3][lr] = av.w;
        *(float4*)&Bs[wk][wc] =
            *(const float4*)(W1e + (size_t)(k0 + wk) * H1D + n0 + wc);
        __syncthreads();

#pragma unroll
        for (int k = 0; k < 16; k++) {
            float a0 = As[k][ty*4 + 0];
            float a1 = As[k][ty*4 + 1];
            float a2 = As[k][ty*4 + 2];
            float a3 = As[k][ty*4 + 3];
            float4 bv = *(const float4*)&Bs[k][tx*4];
            acc[0][0] += a0 * bv.x; acc[0][1] += a0 * bv.y;
            acc[0][2] += a0 * bv.z; acc[0][3] += a0 * bv.w;
            acc[1][0] += a1 * bv.x; acc[1][1] += a1 * bv.y;
            acc[1][2] += a1 * bv.z; acc[1][3] += a1 * bv.w;
            acc[2][0] += a2 * bv.x; acc[2][1] += a2 * bv.y;
            acc[2][2] += a2 * bv.z; acc[2][3] += a2 * bv.w;
            acc[3][0] += a3 * bv.x; acc[3][1] += a3 * bv.y;
            acc[3][2] += a3 * bv.z; acc[3][3] += a3 * bv.w;
        }
        __syncthreads();
    }

    float4 bb = *(const float4*)(b1 + (size_t)e * H1D + n0 + tx*4);
    float* outp = g_h + ((size_t)e * B_DIM + m0) * H1D;
#pragma unroll
    for (int i = 0; i < 4; i++) {
        int r = ty*4 + i;
        float4 v;
        v.x = fmaxf(acc[i][0] + bb.x, 0.f);
        v.y = fmaxf(acc[i][1] + bb.y, 0.f);
        v.z = fmaxf(acc[i][2] + bb.z, 0.f);
        v.w = fmaxf(acc[i][3] + bb.w, 0.f);
        *(float4*)(outp + (size_t)r * H1D + n0 + tx*4) = v;
    }
}

// ---------------------------------------------------------------------------
// Kernel 3: e_out[e] = relu(h[e] @ W2[e] + b2[e]); towers[t] += gates*e_out
// Fused: 32-row tile per CTA, loop over experts, accumulate both tasks.
// 256 threads: ty = tid/32 -> rows ty*4..+3 (32 rows), tx = tid%32 -> cols tx*4..+3 (128 cols)
// grid = B/32
// ---------------------------------------------------------------------------
__global__ void layer2_combine_kernel(const float* __restrict__ W2,
                                      const float* __restrict__ b2,
                                      float* __restrict__ out) {
    __shared__ float hs[32][32];    // h tile [row][k]
    __shared__ float ws[32][128];   // W2 tile [k][col]

    int b0 = blockIdx.x * 32;
    int tid = threadIdx.x;
    int ty = tid >> 5;    // 0..7
    int tx = tid & 31;    // 0..31
    int r0 = ty * 4;
    int c0 = tx * 4;

    float acc0[4][4], acc1[4][4];
#pragma unroll
    for (int i = 0; i < 4; i++)
#pragma unroll
        for (int j = 0; j < 4; j++) { acc0[i][j] = 0.f; acc1[i][j] = 0.f; }

    int hr = tid >> 3;          // h-load row 0..31
    int hc = (tid & 7) * 4;     // h-load k offset

    for (int e = 0; e < E_DIM; e++) {
        float eo[4][4];
#pragma unroll
        for (int i = 0; i < 4; i++)
#pragma unroll
            for (int j = 0; j < 4; j++) eo[i][j] = 0.f;

        const float* hbase = g_h + ((size_t)e * B_DIM + b0) * H1D;
        const float* wbase = W2 + (size_t)e * H1D * H2D;

        for (int kb = 0; kb < H1D; kb += 32) {
            *(float4*)&hs[hr][hc] =
                *(const float4*)(hbase + (size_t)hr * H1D + kb + hc);
#pragma unroll
            for (int j = 0; j < 4; j++) {
                int idx = tid + j * 256;          // float4 index within 32x128 tile
                int wr = idx >> 5;                // k row
                int wc = (idx & 31) * 4;          // col
                *(float4*)&ws[wr][wc] =
                    *(const float4*)(wbase + (size_t)(kb + wr) * H2D + wc);
            }
            __syncthreads();

#pragma unroll
            for (int k = 0; k < 32; k++) {
                float4 wv = *(const float4*)&ws[k][c0];
                float a0 = hs[r0 + 0][k];
                float a1 = hs[r0 + 1][k];
                float a2 = hs[r0 + 2][k];
                float a3 = hs[r0 + 3][k];
                eo[0][0] += a0 * wv.x; eo[0][1] += a0 * wv.y;
                eo[0][2] += a0 * wv.z; eo[0][3] += a0 * wv.w;
                eo[1][0] += a1 * wv.x; eo[1][1] += a1 * wv.y;
                eo[1][2] += a1 * wv.z; eo[1][3] += a1 * wv.w;
                eo[2][0] += a2 * wv.x; eo[2][1] += a2 * wv.y;
                eo[2][2] += a2 * wv.z; eo[2][3] += a2 * wv.w;
                eo[3][0] += a3 * wv.x; eo[3][1] += a3 * wv.y;
                eo[3][2] += a3 * wv.z; eo[3][3] += a3 * wv.w;
            }
            __syncthreads();
        }

        float4 bb = *(const float4*)(b2 + (size_t)e * H2D + c0);
#pragma unroll
        for (int i = 0; i < 4; i++) {
            int b = b0 + r0 + i;
            float gate0 = g_gates[((size_t)0 * B_DIM + b) * E_DIM + e];
            float gate1 = g_gates[((size_t)1 * B_DIM + b) * E_DIM + e];
            float v0 = fmaxf(eo[i][0] + bb.x, 0.f);
            float v1 = fmaxf(eo[i][1] + bb.y, 0.f);
            float v2 = fmaxf(eo[i][2] + bb.z, 0.f);
            float v3 = fmaxf(eo[i][3] + bb.w, 0.f);
            acc0[i][0] += gate0 * v0; acc0[i][1] += gate0 * v1;
            acc0[i][2] += gate0 * v2; acc0[i][3] += gate0 * v3;
            acc1[i][0] += gate1 * v0; acc1[i][1] += gate1 * v1;
            acc1[i][2] += gate1 * v2; acc1[i][3] += gate1 * v3;
        }
    }

#pragma unroll
    for (int i = 0; i < 4; i++) {
        int b = b0 + r0 + i;
        float4 v0, v1;
        v0.x = acc0[i][0]; v0.y = acc0[i][1]; v0.z = acc0[i][2]; v0.w = acc0[i][3];
        v1.x = acc1[i][0]; v1.y = acc1[i][1]; v1.z = acc1[i][2]; v1.w = acc1[i][3];
        *(float4*)(out + ((size_t)0 * B_DIM + b) * H2D + c0) = v0;
        *(float4*)(out + ((size_t)1 * B_DIM + b) * H2D + c0) = v1;
    }
}

// ---------------------------------------------------------------------------
extern "C" void kernel_launch(void* const* d_in, const int* in_sizes, int n_in,
                              void* d_out, int out_size) {
    const float* x  = (const float*)d_in[0];  // [B, I]
    const float* W1 = (const float*)d_in[1];  // [E, I, H1]
    const float* b1 = (const float*)d_in[2];  // [E, H1]
    const float* W2 = (const float*)d_in[3];  // [E, H1, H2]
    const float* b2 = (const float*)d_in[4];  // [E, H2]
    const float* Wg = (const float*)d_in[5];  // [T, I, E]
    const float* bg = (const float*)d_in[6];  // [T, E]
    float* out = (float*)d_out;               // [T, B, H2]

    // gates: one warp per row, 8 warps per block
    gates_kernel<<<B_DIM / 8, 256>>>(x, Wg, bg);

    // layer 1: grouped GEMM
    dim3 g1(B_DIM / 64, H1D / 64, E_DIM);
    layer1_kernel<<<g1, 256>>>(x, W1, b1);

    // layer 2 + gated combine
    layer2_combine_kernel<<<B_DIM / 32, 256>>>(W2, b2, out);
}

// round 6
// speedup vs baseline: 1.0057x; 1.0057x over previous
#include <cuda_runtime.h>

// Problem constants
#define B_DIM 16384
#define I_DIM 512
#define H1D   256
#define H2D   128
#define E_DIM 8
#define T_DIM 2

// Scratch (device globals: allocation-free per harness rules)
__device__ float g_h[(size_t)E_DIM * B_DIM * H1D];        // 134 MB: relu(x@W1+b1)
__device__ float g_gates[(size_t)T_DIM * B_DIM * E_DIM];  // 1 MB: softmaxed gates

// ---------------------------------------------------------------------------
// Kernel 1: per-task gate softmax.  One warp per row b.
// gates[t][b][e] = softmax_e( x[b]·Wg[t,:,e] + bg[t,e] )
// ---------------------------------------------------------------------------
__global__ void gates_kernel(const float* __restrict__ x,
                             const float* __restrict__ Wg,
                             const float* __restrict__ bg) {
    int warp = (blockIdx.x * blockDim.x + threadIdx.x) >> 5;
    int lane = threadIdx.x & 31;
    if (warp >= B_DIM) return;
    int b = warp;
    float acc[16];
#pragma unroll
    for (int j = 0; j < 16; j++) acc[j] = 0.f;

    const float* xr = x + (size_t)b * I_DIM;
#pragma unroll 4
    for (int ii = 0; ii < 16; ii++) {
        int i = ii * 32 + lane;
        float xv = xr[i];
#pragma unroll
        for (int t = 0; t < T_DIM; t++) {
            const float4* wp = (const float4*)(Wg + ((size_t)t * I_DIM + i) * E_DIM);
            float4 w0 = wp[0], w1 = wp[1];
            acc[t*8+0] += xv * w0.x; acc[t*8+1] += xv * w0.y;
            acc[t*8+2] += xv * w0.z; acc[t*8+3] += xv * w0.w;
            acc[t*8+4] += xv * w1.x; acc[t*8+5] += xv * w1.y;
            acc[t*8+6] += xv * w1.z; acc[t*8+7] += xv * w1.w;
        }
    }
#pragma unroll
    for (int j = 0; j < 16; j++) {
#pragma unroll
        for (int off = 16; off > 0; off >>= 1)
            acc[j] += __shfl_xor_sync(0xffffffffu, acc[j], off);
    }
    if (lane == 0) {
#pragma unroll
        for (int t = 0; t < T_DIM; t++) {
            float m = -1e30f;
#pragma unroll
            for (int e = 0; e < E_DIM; e++) {
                float v = acc[t*8+e] + bg[t*E_DIM + e];
                acc[t*8+e] = v;
                m = fmaxf(m, v);
            }
            float ex[E_DIM];
            float s = 0.f;
#pragma unroll
            for (int e = 0; e < E_DIM; e++) { ex[e] = expf(acc[t*8+e] - m); s += ex[e]; }
            float inv = 1.f / s;
#pragma unroll
            for (int e = 0; e < E_DIM; e++)
                g_gates[((size_t)t * B_DIM + b) * E_DIM + e] = ex[e] * inv;
        }
    }
}

// ---------------------------------------------------------------------------
// Kernel 2: h[e] = relu(x @ W1[e] + b1[e])   -> g_h [E, B, H1]
// Tiled GEMM: BM=BN=64, BK=16, 256 threads, 4x4 register micro-tile.
// grid = (B/64, H1/64, E)
// ---------------------------------------------------------------------------
__global__ void layer1_kernel(const float* __restrict__ x,
                              const float* __restrict__ W1,
                              const float* __restrict__ b1) {
    __shared__ float As[16][65];   // As[k][m], padded
    __shared__ float Bs[16][64];   // Bs[k][n]

    int e  = blockIdx.z;
    int n0 = blockIdx.y * 64;
    int m0 = blockIdx.x * 64;
    int tid = threadIdx.x;
    int ty = tid >> 4;        // 0..15  (rows ty*4 .. ty*4+3)
    int tx = tid & 15;        // 0..15  (cols tx*4 .. tx*4+3)

    float acc[4][4];
#pragma unroll
    for (int i = 0; i < 4; i++)
#pragma unroll
        for (int j = 0; j < 4; j++) acc[i][j] = 0.f;

    const float* W1e = W1 + (size_t)e * I_DIM * H1D;

    int lr = tid >> 2;           // A-load row 0..63
    int lc = (tid & 3) * 4;      // A-load k offset 0..12
    int wk = tid >> 4;           // B-load k row 0..15
    int wc = (tid & 15) * 4;     // B-load col offset

    for (int k0 = 0; k0 < I_DIM; k0 += 16) {
        float4 av = *(const float4*)(x + (size_t)(m0 + lr) * I_DIM + k0 + lc);
        As[lc + 0][lr] = av.x;
        As[lc + 1][lr] = av.y;
        As[lc + 2][lr] = av.z;
        As[lc + 3][lr] = av.w;
        *(float4*)&Bs[wk][wc] =
            *(const float4*)(W1e + (size_t)(k0 + wk) * H1D + n0 + wc);
        __syncthreads();

#pragma unroll
        for (int k = 0; k < 16; k++) {
            float a0 = As[k][ty*4 + 0];
            float a1 = As[k][ty*4 + 1];
            float a2 = As[k][ty*4 + 2];
            float a3 = As[k][ty*4 + 3];
            float4 bv = *(const float4*)&Bs[k][tx*4];
            acc[0][0] += a0 * bv.x; acc[0][1] += a0 * bv.y;
            acc[0][2] += a0 * bv.z; acc[0][3] += a0 * bv.w;
            acc[1][0] += a1 * bv.x; acc[1][1] += a1 * bv.y;
            acc[1][2] += a1 * bv.z; acc[1][3] += a1 * bv.w;
            acc[2][0] += a2 * bv.x; acc[2][1] += a2 * bv.y;
            acc[2][2] += a2 * bv.z; acc[2][3] += a2 * bv.w;
            acc[3][0] += a3 * bv.x; acc[3][1] += a3 * bv.y;
            acc[3][2] += a3 * bv.z; acc[3][3] += a3 * bv.w;
        }
        __syncthreads();
    }

    float4 bb = *(const float4*)(b1 + (size_t)e * H1D + n0 + tx*4);
    float* outp = g_h + ((size_t)e * B_DIM + m0) * H1D;
#pragma unroll
    for (int i = 0; i < 4; i++) {
        int r = ty*4 + i;
        float4 v;
        v.x = fmaxf(acc[i][0] + bb.x, 0.f);
        v.y = fmaxf(acc[i][1] + bb.y, 0.f);
        v.z = fmaxf(acc[i][2] + bb.z, 0.f);
        v.w = fmaxf(acc[i][3] + bb.w, 0.f);
        *(float4*)(outp + (size_t)r * H1D + n0 + tx*4) = v;
    }
}

// ---------------------------------------------------------------------------
// Kernel 3: e_out[e] = relu(h[e] @ W2[e] + b2[e]); towers[t] += gates*e_out
// Fused: 32-row tile per CTA, loop over experts, accumulate both tasks.
// 256 threads: ty = tid/32 -> rows ty*4..+3 (32 rows), tx = tid%32 -> cols tx*4..+3 (128 cols)
// grid = B/32
// ---------------------------------------------------------------------------
__global__ void layer2_combine_kernel(const float* __restrict__ W2,
                                      const float* __restrict__ b2,
                                      float* __restrict__ out) {
    __shared__ float hs[32][32];    // h tile [row][k]
    __shared__ float ws[32][128];   // W2 tile [k][col]

    int b0 = blockIdx.x * 32;
    int tid = threadIdx.x;
    int ty = tid >> 5;    // 0..7
    int tx = tid & 31;    // 0..31
    int r0 = ty * 4;
    int c0 = tx * 4;

    float acc0[4][4], acc1[4][4];
#pragma unroll
    for (int i = 0; i < 4; i++)
#pragma unroll
        for (int j = 0; j < 4; j++) { acc0[i][j] = 0.f; acc1[i][j] = 0.f; }

    int hr = tid >> 3;          // h-load row 0..31
    int hc = (tid & 7) * 4;     // h-load k offset

    for (int e = 0; e < E_DIM; e++) {
        float eo[4][4];
#pragma unroll
        for (int i = 0; i < 4; i++)
#pragma unroll
            for (int j = 0; j < 4; j++) eo[i][j] = 0.f;

        const float* hbase = g_h + ((size_t)e * B_DIM + b0) * H1D;
        const float* wbase = W2 + (size_t)e * H1D * H2D;

        for (int kb = 0; kb < H1D; kb += 32) {
            *(float4*)&hs[hr][hc] =
                *(const float4*)(hbase + (size_t)hr * H1D + kb + hc);
#pragma unroll
            for (int j = 0; j < 4; j++) {
                int idx = tid + j * 256;          // float4 index within 32x128 tile
                int wr = idx >> 5;                // k row
                int wc = (idx & 31) * 4;          // col
                *(float4*)&ws[wr][wc] =
                    *(const float4*)(wbase + (size_t)(kb + wr) * H2D + wc);
            }
            __syncthreads();

#pragma unroll
            for (int k = 0; k < 32; k++) {
                float4 wv = *(const float4*)&ws[k][c0];
                float a0 = hs[r0 + 0][k];
                float a1 = hs[r0 + 1][k];
                float a2 = hs[r0 + 2][k];
                float a3 = hs[r0 + 3][k];
                eo[0][0] += a0 * wv.x; eo[0][1] += a0 * wv.y;
                eo[0][2] += a0 * wv.z; eo[0][3] += a0 * wv.w;
                eo[1][0] += a1 * wv.x; eo[1][1] += a1 * wv.y;
                eo[1][2] += a1 * wv.z; eo[1][3] += a1 * wv.w;
                eo[2][0] += a2 * wv.x; eo[2][1] += a2 * wv.y;
                eo[2][2] += a2 * wv.z; eo[2][3] += a2 * wv.w;
                eo[3][0] += a3 * wv.x; eo[3][1] += a3 * wv.y;
                eo[3][2] += a3 * wv.z; eo[3][3] += a3 * wv.w;
            }
            __syncthreads();
        }

        float4 bb = *(const float4*)(b2 + (size_t)e * H2D + c0);
#pragma unroll
        for (int i = 0; i < 4; i++) {
            int b = b0 + r0 + i;
            float gate0 = g_gates[((size_t)0 * B_DIM + b) * E_DIM + e];
            float gate1 = g_gates[((size_t)1 * B_DIM + b) * E_DIM + e];
            float v0 = fmaxf(eo[i][0] + bb.x, 0.f);
            float v1 = fmaxf(eo[i][1] + bb.y, 0.f);
            float v2 = fmaxf(eo[i][2] + bb.z, 0.f);
            float v3 = fmaxf(eo[i][3] + bb.w, 0.f);
            acc0[i][0] += gate0 * v0; acc0[i][1] += gate0 * v1;
            acc0[i][2] += gate0 * v2; acc0[i][3] += gate0 * v3;
            acc1[i][0] += gate1 * v0; acc1[i][1] += gate1 * v1;
            acc1[i][2] += gate1 * v2; acc1[i][3] += gate1 * v3;
        }
    }

#pragma unroll
    for (int i = 0; i < 4; i++) {
        int b = b0 + r0 + i;
        float4 v0, v1;
        v0.x = acc0[i][0]; v0.y = acc0[i][1]; v0.z = acc0[i][2]; v0.w = acc0[i][3];
        v1.x = acc1[i][0]; v1.y = acc1[i][1]; v1.z = acc1[i][2]; v1.w = acc1[i][3];
        *(float4*)(out + ((size_t)0 * B_DIM + b) * H2D + c0) = v0;
        *(float4*)(out + ((size_t)1 * B_DIM + b) * H2D + c0) = v1;
    }
}

// ---------------------------------------------------------------------------
extern "C" void kernel_launch(void* const* d_in, const int* in_sizes, int n_in,
                              void* d_out, int out_size) {
    const float* x  = (const float*)d_in[0];  // [B, I]
    const float* W1 = (const float*)d_in[1];  // [E, I, H1]
    const float* b1 = (const float*)d_in[2];  // [E, H1]
    const float* W2 = (const float*)d_in[3];  // [E, H1, H2]
    const float* b2 = (const float*)d_in[4];  // [E, H2]
    const float* Wg = (const float*)d_in[5];  // [T, I, E]
    const float* bg = (const float*)d_in[6];  // [T, E]
    float* out = (float*)d_out;               // [T, B, H2]

    // gates: one warp per row, 8 warps per block
    gates_kernel<<<B_DIM / 8, 256>>>(x, Wg, bg);

    // layer 1: grouped GEMM
    dim3 g1(B_DIM / 64, H1D / 64, E_DIM);
    layer1_kernel<<<g1, 256>>>(x, W1, b1);

    // layer 2 + gated combine
    layer2_combine_kernel<<<B_DIM / 32, 256>>>(W2, b2, out);
}

// round 9
// speedup vs baseline: 2.9468x; 2.9300x over previous
#include <cuda_runtime.h>
#include <cuda_bf16.h>
#include <cstdint>

// Problem constants
#define B_DIM 16384
#define I_DIM 512
#define H1D   256
#define H2D   128
#define E_DIM 8
#define T_DIM 2

// ---------------------------------------------------------------------------
// Device globals (allocation-free scratch)
// ---------------------------------------------------------------------------
__device__ __nv_bfloat16 g_x_hi[(size_t)B_DIM * I_DIM];
__device__ __nv_bfloat16 g_x_lo[(size_t)B_DIM * I_DIM];
__device__ __nv_bfloat16 g_w1t_hi[(size_t)E_DIM * H1D * I_DIM];   // [E][H1][I]
__device__ __nv_bfloat16 g_w1t_lo[(size_t)E_DIM * H1D * I_DIM];
__device__ __nv_bfloat16 g_w2t_hi[(size_t)E_DIM * H2D * H1D];     // [E][H2][H1]
__device__ __nv_bfloat16 g_w2t_lo[(size_t)E_DIM * H2D * H1D];
__device__ __nv_bfloat16 g_h_hi[(size_t)E_DIM * B_DIM * H1D];     // [E][B][H1]
__device__ __nv_bfloat16 g_h_lo[(size_t)E_DIM * B_DIM * H1D];
__device__ float         g_eout[(size_t)E_DIM * B_DIM * H2D];     // [E][B][H2]
__device__ float         g_gates[(size_t)T_DIM * B_DIM * E_DIM];

// ---------------------------------------------------------------------------
// Helpers (sm_80+ features only — environment compiles virtual compute_103,
// which rejects all tcgen05/*a* instructions)
// ---------------------------------------------------------------------------
__device__ __forceinline__ uint32_t smem_u32(const void* p) {
    uint32_t a;
    asm("{ .reg .u64 t; cvta.to.shared.u64 t, %1; cvt.u32.u64 %0, t; }"
        : "=r"(a) : "l"(p));
    return a;
}

// 128B-period XOR swizzle: 16B atom index ^= (row & 7)
#define SWZ(o) ((uint32_t)(o) ^ ((((uint32_t)(o)) >> 3) & 0x70u))

__device__ __forceinline__ void cp16(uint32_t s, const void* g) {
    asm volatile("cp.async.cg.shared.global [%0], [%1], 16;"
                 :: "r"(s), "l"(__cvta_generic_to_global(g)));
}
#define CP_COMMIT() asm volatile("cp.async.commit_group;" ::: "memory")

__device__ __forceinline__ void ldsm4(uint32_t* r, uint32_t addr) {
    asm volatile("ldmatrix.sync.aligned.m8n8.x4.shared.b16 {%0,%1,%2,%3}, [%4];"
                 : "=r"(r[0]), "=r"(r[1]), "=r"(r[2]), "=r"(r[3]) : "r"(addr));
}

__device__ __forceinline__ void mma16816(float* d, const uint32_t* a, const uint32_t* b) {
    asm volatile("mma.sync.aligned.m16n8k16.row.col.f32.bf16.bf16.f32 "
                 "{%0,%1,%2,%3}, {%4,%5,%6,%7}, {%8,%9}, {%0,%1,%2,%3};"
                 : "+f"(d[0]), "+f"(d[1]), "+f"(d[2]), "+f"(d[3])
                 : "r"(a[0]), "r"(a[1]), "r"(a[2]), "r"(a[3]), "r"(b[0]), "r"(b[1]));
}

__device__ __forceinline__ void split_bf16(float v, __nv_bfloat16& hi, __nv_bfloat16& lo) {
    hi = __float2bfloat16(v);
    lo = __float2bfloat16(v - __bfloat162float(hi));
}

// ---------------------------------------------------------------------------
// Shared GEMM compute core.
// Smem tile layout per stage (64KB): A_hi @0, A_lo @16K, B_hi @32K, B_lo @48K.
// Each tile: 128 rows x 64 bf16 cols, pitch 128B, swizzled.
// Warp grid: 8 warps = 4(m) x 2(n); warp tile 32(m) x 64(n); 2x8 m16n8 tiles.
// 3 MMAs per (mt,nt,kstep): hi*hi + hi*lo + lo*hi.
// ---------------------------------------------------------------------------
#define G_STAGE 65536

__device__ __forceinline__ void gemm_compute(uint32_t sb, int wm, int wn, int L,
                                             float acc[2][8][4]) {
#pragma unroll
    for (int ks = 0; ks < 4; ks++) {
        uint32_t afh[2][4], afl[2][4], bfh[8][2], bfl[8][2];
#pragma unroll
        for (int mt = 0; mt < 2; mt++) {
            int row = wm + mt * 16 + (L & 15);
            int co = ks * 32 + ((L >> 4) & 1) * 16;
            ldsm4(afh[mt], sb + 0u     + SWZ(row * 128 + co));
            ldsm4(afl[mt], sb + 16384u + SWZ(row * 128 + co));
        }
#pragma unroll
        for (int np = 0; np < 4; np++) {
            int g = L >> 3;
            int n = wn + np * 16 + (g >> 1) * 8 + (L & 7);
            int co = ks * 32 + (g & 1) * 16;
            uint32_t r[4];
            ldsm4(r, sb + 32768u + SWZ(n * 128 + co));
            bfh[np * 2][0] = r[0]; bfh[np * 2][1] = r[1];
            bfh[np * 2 + 1][0] = r[2]; bfh[np * 2 + 1][1] = r[3];
            ldsm4(r, sb + 49152u + SWZ(n * 128 + co));
            bfl[np * 2][0] = r[0]; bfl[np * 2][1] = r[1];
            bfl[np * 2 + 1][0] = r[2]; bfl[np * 2 + 1][1] = r[3];
        }
#pragma unroll
        for (int mt = 0; mt < 2; mt++)
#pragma unroll
            for (int nt = 0; nt < 8; nt++) {
                mma16816(acc[mt][nt], afh[mt], bfh[nt]);
                mma16816(acc[mt][nt], afh[mt], bfl[nt]);
                mma16816(acc[mt][nt], afl[mt], bfh[nt]);
            }
    }
}

// Loader: 4096 x 16B cp.async per chunk (A_hi/A_lo/B_hi/B_lo, 1024 each).
// t = 0..15 per thread; mat = t>>2 is compile-time in the unrolled loop.
template<int PITCH>
__device__ __forceinline__ void gemm_load(uint32_t smb, int stage, int tid, int k0,
                                          const __nv_bfloat16* Ah, const __nv_bfloat16* Al,
                                          const __nv_bfloat16* Bh, const __nv_bfloat16* Bl) {
    uint32_t sb = smb + (uint32_t)stage * G_STAGE;
#pragma unroll
    for (int t = 0; t < 16; t++) {
        const int mat = t >> 2;
        const __nv_bfloat16* p = (mat == 0) ? Ah : (mat == 1) ? Al : (mat == 2) ? Bh : Bl;
        int j = (t & 3) * 256 + tid;
        int row = j >> 3, c8 = j & 7;
        cp16(sb + (uint32_t)mat * 16384u + SWZ(row * 128 + c8 * 16),
             p + (size_t)row * PITCH + k0 + c8 * 8);
    }
    CP_COMMIT();
}

// ---------------------------------------------------------------------------
// GEMM1: C[b][h1] = x[b][:] . w1t[h1][:]  (per expert), +b1, relu,
// split -> g_h_hi/g_h_lo [E][B][H1].  K=512, 8 chunks.
// grid = (B/128, H1/128, E), 256 threads.
// ---------------------------------------------------------------------------
__global__ void __launch_bounds__(256, 1)
gemm1_kernel(const float* __restrict__ b1) {
    extern __shared__ char sm[];
    uint32_t smb = smem_u32(sm);
    const int e = blockIdx.z, b0 = blockIdx.x * 128, n0 = blockIdx.y * 128;
    const int tid = threadIdx.x, L = tid & 31, w = tid >> 5;
    const int wm = (w >> 1) * 32, wn = (w & 1) * 64;

    const __nv_bfloat16* Ah = g_x_hi + (size_t)b0 * I_DIM;
    const __nv_bfloat16* Al = g_x_lo + (size_t)b0 * I_DIM;
    const __nv_bfloat16* Bh = g_w1t_hi + ((size_t)e * H1D + n0) * I_DIM;
    const __nv_bfloat16* Bl = g_w1t_lo + ((size_t)e * H1D + n0) * I_DIM;

    float acc[2][8][4];
#pragma unroll
    for (int mt = 0; mt < 2; mt++)
#pragma unroll
        for (int nt = 0; nt < 8; nt++)
#pragma unroll
            for (int q = 0; q < 4; q++) acc[mt][nt][q] = 0.f;

    gemm_load<I_DIM>(smb, 0, tid, 0, Ah, Al, Bh, Bl);
    for (int c = 0; c < 8; c++) {
        if (c < 7) {
            gemm_load<I_DIM>(smb, (c + 1) & 1, tid, (c + 1) * 64, Ah, Al, Bh, Bl);
            asm volatile("cp.async.wait_group 1;" ::: "memory");
        } else {
            asm volatile("cp.async.wait_group 0;" ::: "memory");
        }
        __syncthreads();
        gemm_compute(smb + (uint32_t)(c & 1) * G_STAGE, wm, wn, L, acc);
        __syncthreads();
    }

    // Epilogue: bias + relu + hi/lo split -> g_h
    float bias[8][2];
#pragma unroll
    for (int nt = 0; nt < 8; nt++) {
        int gn = n0 + wn + nt * 8 + 2 * (L & 3);
        bias[nt][0] = b1[e * H1D + gn];
        bias[nt][1] = b1[e * H1D + gn + 1];
    }
#pragma unroll
    for (int mt = 0; mt < 2; mt++) {
        int gb = b0 + wm + mt * 16 + (L >> 2);
#pragma unroll
        for (int nt = 0; nt < 8; nt++) {
            int gn = n0 + wn + nt * 8 + 2 * (L & 3);
            float v00 = fmaxf(acc[mt][nt][0] + bias[nt][0], 0.f);
            float v01 = fmaxf(acc[mt][nt][1] + bias[nt][1], 0.f);
            float v10 = fmaxf(acc[mt][nt][2] + bias[nt][0], 0.f);
            float v11 = fmaxf(acc[mt][nt][3] + bias[nt][1], 0.f);
            __nv_bfloat16 h00, l00, h01, l01, h10, l10, h11, l11;
            split_bf16(v00, h00, l00); split_bf16(v01, h01, l01);
            split_bf16(v10, h10, l10); split_bf16(v11, h11, l11);
            size_t o0 = ((size_t)e * B_DIM + gb) * H1D + gn;
            size_t o1 = o0 + (size_t)8 * H1D;
            __nv_bfloat162 ph0; ph0.x = h00; ph0.y = h01;
            __nv_bfloat162 pl0; pl0.x = l00; pl0.y = l01;
            __nv_bfloat162 ph1; ph1.x = h10; ph1.y = h11;
            __nv_bfloat162 pl1; pl1.x = l10; pl1.y = l11;
            *(__nv_bfloat162*)(g_h_hi + o0) = ph0;
            *(__nv_bfloat162*)(g_h_lo + o0) = pl0;
            *(__nv_bfloat162*)(g_h_hi + o1) = ph1;
            *(__nv_bfloat162*)(g_h_lo + o1) = pl1;
        }
    }
}

// ---------------------------------------------------------------------------
// GEMM2: C[b][h2] = h[b][:] . w2t[h2][:]  (per expert), +b2, relu
// -> g_eout [E][B][H2] f32.  K=256, 4 chunks.
// grid = (B/128, 1, E), 256 threads.
// ---------------------------------------------------------------------------
__global__ void __launch_bounds__(256, 1)
gemm2_kernel(const float* __restrict__ b2) {
    extern __shared__ char sm[];
    uint32_t smb = smem_u32(sm);
    const int e = blockIdx.z, b0 = blockIdx.x * 128;
    const int tid = threadIdx.x, L = tid & 31, w = tid >> 5;
    const int wm = (w >> 1) * 32, wn = (w & 1) * 64;

    const __nv_bfloat16* Ah = g_h_hi + ((size_t)e * B_DIM + b0) * H1D;
    const __nv_bfloat16* Al = g_h_lo + ((size_t)e * B_DIM + b0) * H1D;
    const __nv_bfloat16* Bh = g_w2t_hi + (size_t)e * H2D * H1D;
    const __nv_bfloat16* Bl = g_w2t_lo + (size_t)e * H2D * H1D;

    float acc[2][8][4];
#pragma unroll
    for (int mt = 0; mt < 2; mt++)
#pragma unroll
        for (int nt = 0; nt < 8; nt++)
#pragma unroll
            for (int q = 0; q < 4; q++) acc[mt][nt][q] = 0.f;

    gemm_load<H1D>(smb, 0, tid, 0, Ah, Al, Bh, Bl);
    for (int c = 0; c < 4; c++) {
        if (c < 3) {
            gemm_load<H1D>(smb, (c + 1) & 1, tid, (c + 1) * 64, Ah, Al, Bh, Bl);
            asm volatile("cp.async.wait_group 1;" ::: "memory");
        } else {
            asm volatile("cp.async.wait_group 0;" ::: "memory");
        }
        __syncthreads();
        gemm_compute(smb + (uint32_t)(c & 1) * G_STAGE, wm, wn, L, acc);
        __syncthreads();
    }

    float bias[8][2];
#pragma unroll
    for (int nt = 0; nt < 8; nt++) {
        int gn = wn + nt * 8 + 2 * (L & 3);
        bias[nt][0] = b2[e * H2D + gn];
        bias[nt][1] = b2[e * H2D + gn + 1];
    }
#pragma unroll
    for (int mt = 0; mt < 2; mt++) {
        int gb = b0 + wm + mt * 16 + (L >> 2);
#pragma unroll
        for (int nt = 0; nt < 8; nt++) {
            int gn = wn + nt * 8 + 2 * (L & 3);
            float v00 = fmaxf(acc[mt][nt][0] + bias[nt][0], 0.f);
            float v01 = fmaxf(acc[mt][nt][1] + bias[nt][1], 0.f);
            float v10 = fmaxf(acc[mt][nt][2] + bias[nt][0], 0.f);
            float v11 = fmaxf(acc[mt][nt][3] + bias[nt][1], 0.f);
            size_t o0 = ((size_t)e * B_DIM + gb) * H2D + gn;
            size_t o1 = o0 + (size_t)8 * H2D;
            *(float2*)(g_eout + o0) = make_float2(v00, v01);
            *(float2*)(g_eout + o1) = make_float2(v10, v11);
        }
    }
}

// ---------------------------------------------------------------------------
// Prep: split x into hi/lo bf16
// ---------------------------------------------------------------------------
__global__ void split_x_kernel(const float* __restrict__ x) {
    size_t idx = (size_t)blockIdx.x * blockDim.x + threadIdx.x;  // one per 4 elems
    float4 v = ((const float4*)x)[idx];
    __nv_bfloat16 h0, l0, h1, l1, h2, l2, h3, l3;
    split_bf16(v.x, h0, l0); split_bf16(v.y, h1, l1);
    split_bf16(v.z, h2, l2); split_bf16(v.w, h3, l3);
    __nv_bfloat162 ph0, ph1, pl0, pl1;
    ph0.x = h0; ph0.y = h1; ph1.x = h2; ph1.y = h3;
    pl0.x = l0; pl0.y = l1; pl1.x = l2; pl1.y = l3;
    ((__nv_bfloat162*)g_x_hi)[idx * 2 + 0] = ph0;
    ((__nv_bfloat162*)g_x_hi)[idx * 2 + 1] = ph1;
    ((__nv_bfloat162*)g_x_lo)[idx * 2 + 0] = pl0;
    ((__nv_bfloat162*)g_x_lo)[idx * 2 + 1] = pl1;
}

// Transpose+split W1 [E][I][H1] -> w1t [E][H1][I]
__global__ void prep_w1_kernel(const float* __restrict__ W1) {
    __shared__ float t[32][33];
    int e = blockIdx.z, h0 = blockIdx.x * 32, i0 = blockIdx.y * 32;
    int tx = threadIdx.x, ty = threadIdx.y;
    const float* src = W1 + (size_t)e * I_DIM * H1D;
#pragma unroll
    for (int j = 0; j < 4; j++)
        t[ty + j * 8][tx] = src[(size_t)(i0 + ty + j * 8) * H1D + h0 + tx];
    __syncthreads();
#pragma unroll
    for (int j = 0; j < 4; j++) {
        float v = t[tx][ty + j * 8];
        __nv_bfloat16 hi, lo; split_bf16(v, hi, lo);
        size_t o = ((size_t)e * H1D + h0 + ty + j * 8) * I_DIM + i0 + tx;
        g_w1t_hi[o] = hi; g_w1t_lo[o] = lo;
    }
}

// Transpose+split W2 [E][H1][H2] -> w2t [E][H2][H1]
__global__ void prep_w2_kernel(const float* __restrict__ W2) {
    __shared__ float t[32][33];
    int e = blockIdx.z, h2_0 = blockIdx.x * 32, h1_0 = blockIdx.y * 32;
    int tx = threadIdx.x, ty = threadIdx.y;
    const float* src = W2 + (size_t)e * H1D * H2D;
#pragma unroll
    for (int j = 0; j < 4; j++)
        t[ty + j * 8][tx] = src[(size_t)(h1_0 + ty + j * 8) * H2D + h2_0 + tx];
    __syncthreads();
#pragma unroll
    for (int j = 0; j < 4; j++) {
        float v = t[tx][ty + j * 8];
        __nv_bfloat16 hi, lo; split_bf16(v, hi, lo);
        size_t o = ((size_t)e * H2D + h2_0 + ty + j * 8) * H1D + h1_0 + tx;
        g_w2t_hi[o] = hi; g_w2t_lo[o] = lo;
    }
}

// ---------------------------------------------------------------------------
// Gates (fp32 SIMT — small)
// ---------------------------------------------------------------------------
__global__ void gates_kernel(const float* __restrict__ x,
                             const float* __restrict__ Wg,
                             const float* __restrict__ bg) {
    int warp = (blockIdx.x * blockDim.x + threadIdx.x) >> 5;
    int lane = threadIdx.x & 31;
    if (warp >= B_DIM) return;
    int b = warp;
    float acc[16];
#pragma unroll
    for (int j = 0; j < 16; j++) acc[j] = 0.f;
    const float* xr = x + (size_t)b * I_DIM;
#pragma unroll 4
    for (int ii = 0; ii < 16; ii++) {
        int i = ii * 32 + lane;
        float xv = xr[i];
#pragma unroll
        for (int t = 0; t < T_DIM; t++) {
            const float4* wp = (const float4*)(Wg + ((size_t)t * I_DIM + i) * E_DIM);
            float4 w0 = wp[0], w1 = wp[1];
            acc[t*8+0] += xv * w0.x; acc[t*8+1] += xv * w0.y;
            acc[t*8+2] += xv * w0.z; acc[t*8+3] += xv * w0.w;
            acc[t*8+4] += xv * w1.x; acc[t*8+5] += xv * w1.y;
            acc[t*8+6] += xv * w1.z; acc[t*8+7] += xv * w1.w;
        }
    }
#pragma unroll
    for (int j = 0; j < 16; j++)
#pragma unroll
        for (int off = 16; off > 0; off >>= 1)
            acc[j] += __shfl_xor_sync(0xffffffffu, acc[j], off);
    if (lane == 0) {
#pragma unroll
        for (int t = 0; t < T_DIM; t++) {
            float m = -1e30f;
#pragma unroll
            for (int e = 0; e < E_DIM; e++) {
                float v = acc[t*8+e] + bg[t*E_DIM + e];
                acc[t*8+e] = v; m = fmaxf(m, v);
            }
            float ex[E_DIM], s = 0.f;
#pragma unroll
            for (int e = 0; e < E_DIM; e++) { ex[e] = expf(acc[t*8+e] - m); s += ex[e]; }
            float inv = 1.f / s;
#pragma unroll
            for (int e = 0; e < E_DIM; e++)
                g_gates[((size_t)t * B_DIM + b) * E_DIM + e] = ex[e] * inv;
        }
    }
}

// ---------------------------------------------------------------------------
// Combine: out[t][b][:] = sum_e gates[t][b][e] * eout[e][b][:]
// ---------------------------------------------------------------------------
__global__ void combine_kernel(float* __restrict__ out) {
    int t = blockIdx.x * blockDim.x + threadIdx.x;  // over B * (H2/4)
    int b = t >> 5, c4 = (t & 31) * 4;
    const float* gp0 = g_gates + (size_t)b * E_DIM;
    const float* gp1 = g_gates + ((size_t)B_DIM + b) * E_DIM;
    float4 a0 = make_float4(0.f, 0.f, 0.f, 0.f);
    float4 a1 = make_float4(0.f, 0.f, 0.f, 0.f);
#pragma unroll
    for (int e = 0; e < E_DIM; e++) {
        float4 v = *(const float4*)(g_eout + ((size_t)e * B_DIM + b) * H2D + c4);
        float g0 = gp0[e], g1 = gp1[e];
        a0.x += g0 * v.x; a0.y += g0 * v.y; a0.z += g0 * v.z; a0.w += g0 * v.w;
        a1.x += g1 * v.x; a1.y += g1 * v.y; a1.z += g1 * v.z; a1.w += g1 * v.w;
    }
    *(float4*)(out + (size_t)b * H2D + c4) = a0;
    *(float4*)(out + ((size_t)B_DIM + b) * H2D + c4) = a1;
}

// ---------------------------------------------------------------------------
extern "C" void kernel_launch(void* const* d_in, const int* in_sizes, int n_in,
                              void* d_out, int out_size) {
    const float* x  = (const float*)d_in[0];
    const float* W1 = (const float*)d_in[1];
    const float* b1 = (const float*)d_in[2];
    const float* W2 = (const float*)d_in[3];
    const float* b2 = (const float*)d_in[4];
    const float* Wg = (const float*)d_in[5];
    const float* bg = (const float*)d_in[6];
    float* out = (float*)d_out;

    const int smem = 2 * G_STAGE;  // 128KB double-buffered stages
    cudaFuncSetAttribute(gemm1_kernel, cudaFuncAttributeMaxDynamicSharedMemorySize, smem);
    cudaFuncSetAttribute(gemm2_kernel, cudaFuncAttributeMaxDynamicSharedMemorySize, smem);

    split_x_kernel<<<(B_DIM * I_DIM / 4) / 256, 256>>>(x);
    prep_w1_kernel<<<dim3(H1D / 32, I_DIM / 32, E_DIM), dim3(32, 8)>>>(W1);
    prep_w2_kernel<<<dim3(H2D / 32, H1D / 32, E_DIM), dim3(32, 8)>>>(W2);
    gates_kernel<<<B_DIM / 8, 256>>>(x, Wg, bg);

    gemm1_kernel<<<dim3(B_DIM / 128, H1D / 128, E_DIM), 256, smem>>>(b1);
    gemm2_kernel<<<dim3(B_DIM / 128, 1, E_DIM), 256, smem>>>(b2);
    combine_kernel<<<(B_DIM * (H2D / 4)) / 256, 256>>>(out);
}

// round 10
// speedup vs baseline: 3.2414x; 1.1000x over previous
#include <cuda_runtime.h>
#include <cuda_bf16.h>
#include <cstdint>

// Problem constants
#define B_DIM 16384
#define I_DIM 512
#define H1D   256
#define H2D   128
#define E_DIM 8
#define T_DIM 2

// ---------------------------------------------------------------------------
// Device globals (allocation-free scratch)
// ---------------------------------------------------------------------------
__device__ __nv_bfloat16 g_x_hi[(size_t)B_DIM * I_DIM];
__device__ __nv_bfloat16 g_x_lo[(size_t)B_DIM * I_DIM];
__device__ __nv_bfloat16 g_w1t_hi[(size_t)E_DIM * H1D * I_DIM];   // [E][H1][I]
__device__ __nv_bfloat16 g_w1t_lo[(size_t)E_DIM * H1D * I_DIM];
__device__ __nv_bfloat16 g_w2t_hi[(size_t)E_DIM * H2D * H1D];     // [E][H2][H1]
__device__ __nv_bfloat16 g_w2t_lo[(size_t)E_DIM * H2D * H1D];
__device__ __nv_bfloat16 g_wgt_hi[16 * I_DIM];                    // [t*8+e][I]
__device__ __nv_bfloat16 g_wgt_lo[16 * I_DIM];
__device__ __nv_bfloat16 g_h_hi[(size_t)E_DIM * B_DIM * H1D];     // [E][B][H1]
__device__ __nv_bfloat16 g_h_lo[(size_t)E_DIM * B_DIM * H1D];
__device__ float         g_glogits[(size_t)B_DIM * 16];           // [B][t*8+e]
__device__ float         g_gates[(size_t)T_DIM * B_DIM * E_DIM];  // [T][B][E]

// ---------------------------------------------------------------------------
// Helpers (sm_80+ only — environment compiles virtual compute_103, which
// rejects all tcgen05/sm_103a-suffix instructions)
// ---------------------------------------------------------------------------
__device__ __forceinline__ uint32_t smem_u32(const void* p) {
    uint32_t a;
    asm("{ .reg .u64 t; cvta.to.shared.u64 t, %1; cvt.u32.u64 %0, t; }"
        : "=r"(a) : "l"(p));
    return a;
}

// 128B-period XOR swizzle
#define SWZ(o) ((uint32_t)(o) ^ ((((uint32_t)(o)) >> 3) & 0x70u))

__device__ __forceinline__ void cp16(uint32_t s, const void* g) {
    asm volatile("cp.async.cg.shared.global [%0], [%1], 16;"
                 :: "r"(s), "l"(__cvta_generic_to_global(g)));
}
#define CP_COMMIT() asm volatile("cp.async.commit_group;" ::: "memory")

__device__ __forceinline__ void ldsm4(uint32_t* r, uint32_t addr) {
    asm volatile("ldmatrix.sync.aligned.m8n8.x4.shared.b16 {%0,%1,%2,%3}, [%4];"
                 : "=r"(r[0]), "=r"(r[1]), "=r"(r[2]), "=r"(r[3]) : "r"(addr));
}

__device__ __forceinline__ void mma16816(float* d, const uint32_t* a, const uint32_t* b) {
    asm volatile("mma.sync.aligned.m16n8k16.row.col.f32.bf16.bf16.f32 "
                 "{%0,%1,%2,%3}, {%4,%5,%6,%7}, {%8,%9}, {%0,%1,%2,%3};"
                 : "+f"(d[0]), "+f"(d[1]), "+f"(d[2]), "+f"(d[3])
                 : "r"(a[0]), "r"(a[1]), "r"(a[2]), "r"(a[3]), "r"(b[0]), "r"(b[1]));
}

__device__ __forceinline__ void split_bf16(float v, __nv_bfloat16& hi, __nv_bfloat16& lo) {
    hi = __float2bfloat16(v);
    lo = __float2bfloat16(v - __bfloat162float(hi));
}

// ---------------------------------------------------------------------------
// GEMM1 stage layout (69632 B):
//   A_hi @0 (16K) | A_lo @16K | B_hi @32K | B_lo @48K | Wg_hi @64K (2K) | Wg_lo @66K
// Tiles: A 128x64, B 128x64, Wg 16x64; pitch 128B, swizzled.
// Warp grid: 8 warps = 4(m) x 2(n); warp tile 32x64 = 2x8 m16n8 tiles.
// ---------------------------------------------------------------------------
#define G1_STAGE 69632

__device__ __forceinline__ void gemm1_compute(uint32_t sb, int wm, int wn, int L,
                                              float acc[2][8][4],
                                              bool gate, float gacc[2][2][4]) {
#pragma unroll
    for (int ks = 0; ks < 4; ks++) {
        uint32_t afh[2][4], afl[2][4], bfh[8][2], bfl[8][2];
#pragma unroll
        for (int mt = 0; mt < 2; mt++) {
            int row = wm + mt * 16 + (L & 15);
            int co = ks * 32 + ((L >> 4) & 1) * 16;
            ldsm4(afh[mt], sb + 0u     + SWZ(row * 128 + co));
            ldsm4(afl[mt], sb + 16384u + SWZ(row * 128 + co));
        }
#pragma unroll
        for (int np = 0; np < 4; np++) {
            int g = L >> 3;
            int n = wn + np * 16 + (g >> 1) * 8 + (L & 7);
            int co = ks * 32 + (g & 1) * 16;
            uint32_t r[4];
            ldsm4(r, sb + 32768u + SWZ(n * 128 + co));
            bfh[np * 2][0] = r[0]; bfh[np * 2][1] = r[1];
            bfh[np * 2 + 1][0] = r[2]; bfh[np * 2 + 1][1] = r[3];
            ldsm4(r, sb + 49152u + SWZ(n * 128 + co));
            bfl[np * 2][0] = r[0]; bfl[np * 2][1] = r[1];
            bfl[np * 2 + 1][0] = r[2]; bfl[np * 2 + 1][1] = r[3];
        }
#pragma unroll
        for (int mt = 0; mt < 2; mt++)
#pragma unroll
            for (int nt = 0; nt < 8; nt++) {
                mma16816(acc[mt][nt], afh[mt], bfh[nt]);
                mma16816(acc[mt][nt], afh[mt], bfl[nt]);
                mma16816(acc[mt][nt], afl[mt], bfh[nt]);
            }
        if (gate) {
            int g = L >> 3;
            int n = (g >> 1) * 8 + (L & 7);
            int co = ks * 32 + (g & 1) * 16;
            uint32_t rh[4], rl[4];
            ldsm4(rh, sb + 65536u + SWZ(n * 128 + co));
            ldsm4(rl, sb + 67584u + SWZ(n * 128 + co));
            uint32_t gbh[2][2] = {{rh[0], rh[1]}, {rh[2], rh[3]}};
            uint32_t gbl[2][2] = {{rl[0], rl[1]}, {rl[2], rl[3]}};
#pragma unroll
            for (int mt = 0; mt < 2; mt++)
#pragma unroll
                for (int gt = 0; gt < 2; gt++) {
                    mma16816(gacc[mt][gt], afh[mt], gbh[gt]);
                    mma16816(gacc[mt][gt], afh[mt], gbl[gt]);
                    mma16816(gacc[mt][gt], afl[mt], gbh[gt]);
                }
        }
    }
}

__device__ __forceinline__ void gemm1_load(uint32_t smb, int stage, int tid, int k0,
                                           const __nv_bfloat16* Ah, const __nv_bfloat16* Al,
                                           const __nv_bfloat16* Bh, const __nv_bfloat16* Bl,
                                           bool gate) {
    uint32_t sb = smb + (uint32_t)stage * G1_STAGE;
#pragma unroll
    for (int t = 0; t < 16; t++) {
        const int mat = t >> 2;
        const __nv_bfloat16* p = (mat == 0) ? Ah : (mat == 1) ? Al : (mat == 2) ? Bh : Bl;
        int j = (t & 3) * 256 + tid;
        int row = j >> 3, c8 = j & 7;
        cp16(sb + (uint32_t)mat * 16384u + SWZ(row * 128 + c8 * 16),
             p + (size_t)row * I_DIM + k0 + c8 * 8);
    }
    if (gate) {
        // 256 granules: 16 rows x 8 c8 x {hi,lo}
        int mat = tid >> 7, jj = tid & 127;
        int row = jj >> 3, c8 = jj & 7;
        const __nv_bfloat16* p = mat ? g_wgt_lo : g_wgt_hi;
        cp16(sb + 65536u + (uint32_t)mat * 2048u + SWZ(row * 128 + c8 * 16),
             p + (size_t)row * I_DIM + k0 + c8 * 8);
    }
    CP_COMMIT();
}

// ---------------------------------------------------------------------------
// GEMM1: C[b][h1] = x[b][:] . w1t[h1][:]  (per expert), +b1, relu,
// split -> g_h_hi/g_h_lo.  Gate CTAs (n0==0,e==0) also emit x@Wg^T logits.
// grid = (B/128, H1/128, E), 256 threads.
// ---------------------------------------------------------------------------
__global__ void __launch_bounds__(256, 1)
gemm1_kernel(const float* __restrict__ b1) {
    extern __shared__ char sm[];
    uint32_t smb = smem_u32(sm);
    const int e = blockIdx.z, b0 = blockIdx.x * 128, n0 = blockIdx.y * 128;
    const int tid = threadIdx.x, L = tid & 31, w = tid >> 5;
    const int wm = (w >> 1) * 32, wn = (w & 1) * 64;
    const bool gate = (blockIdx.y == 0) && (blockIdx.z == 0);

    const __nv_bfloat16* Ah = g_x_hi + (size_t)b0 * I_DIM;
    const __nv_bfloat16* Al = g_x_lo + (size_t)b0 * I_DIM;
    const __nv_bfloat16* Bh = g_w1t_hi + ((size_t)e * H1D + n0) * I_DIM;
    const __nv_bfloat16* Bl = g_w1t_lo + ((size_t)e * H1D + n0) * I_DIM;

    float acc[2][8][4];
    float gacc[2][2][4];
#pragma unroll
    for (int mt = 0; mt < 2; mt++) {
#pragma unroll
        for (int nt = 0; nt < 8; nt++)
#pragma unroll
            for (int q = 0; q < 4; q++) acc[mt][nt][q] = 0.f;
#pragma unroll
        for (int gt = 0; gt < 2; gt++)
#pragma unroll
            for (int q = 0; q < 4; q++) gacc[mt][gt][q] = 0.f;
    }

    gemm1_load(smb, 0, tid, 0, Ah, Al, Bh, Bl, gate);
    for (int c = 0; c < 8; c++) {
        if (c < 7) {
            gemm1_load(smb, (c + 1) & 1, tid, (c + 1) * 64, Ah, Al, Bh, Bl, gate);
            asm volatile("cp.async.wait_group 1;" ::: "memory");
        } else {
            asm volatile("cp.async.wait_group 0;" ::: "memory");
        }
        __syncthreads();
        gemm1_compute(smb + (uint32_t)(c & 1) * G1_STAGE, wm, wn, L, acc, gate, gacc);
        __syncthreads();
    }

    // Epilogue: bias + relu + hi/lo split -> g_h
    float bias[8][2];
#pragma unroll
    for (int nt = 0; nt < 8; nt++) {
        int gn = n0 + wn + nt * 8 + 2 * (L & 3);
        bias[nt][0] = b1[e * H1D + gn];
        bias[nt][1] = b1[e * H1D + gn + 1];
    }
#pragma unroll
    for (int mt = 0; mt < 2; mt++) {
        int gb = b0 + wm + mt * 16 + (L >> 2);
#pragma unroll
        for (int nt = 0; nt < 8; nt++) {
            int gn = n0 + wn + nt * 8 + 2 * (L & 3);
            float v00 = fmaxf(acc[mt][nt][0] + bias[nt][0], 0.f);
            float v01 = fmaxf(acc[mt][nt][1] + bias[nt][1], 0.f);
            float v10 = fmaxf(acc[mt][nt][2] + bias[nt][0], 0.f);
            float v11 = fmaxf(acc[mt][nt][3] + bias[nt][1], 0.f);
            __nv_bfloat16 h00, l00, h01, l01, h10, l10, h11, l11;
            split_bf16(v00, h00, l00); split_bf16(v01, h01, l01);
            split_bf16(v10, h10, l10); split_bf16(v11, h11, l11);
            size_t o0 = ((size_t)e * B_DIM + gb) * H1D + gn;
            size_t o1 = o0 + (size_t)8 * H1D;
            __nv_bfloat162 ph0; ph0.x = h00; ph0.y = h01;
            __nv_bfloat162 pl0; pl0.x = l00; pl0.y = l01;
            __nv_bfloat162 ph1; ph1.x = h10; ph1.y = h11;
            __nv_bfloat162 pl1; pl1.x = l10; pl1.y = l11;
            *(__nv_bfloat162*)(g_h_hi + o0) = ph0;
            *(__nv_bfloat162*)(g_h_lo + o0) = pl0;
            *(__nv_bfloat162*)(g_h_hi + o1) = ph1;
            *(__nv_bfloat162*)(g_h_lo + o1) = pl1;
        }
    }
    if (gate) {
#pragma unroll
        for (int mt = 0; mt < 2; mt++) {
            int gb = b0 + wm + mt * 16 + (L >> 2);
#pragma unroll
            for (int gt = 0; gt < 2; gt++) {
                int gc = gt * 8 + 2 * (L & 3);
                *(float2*)(g_glogits + (size_t)gb * 16 + gc) =
                    make_float2(gacc[mt][gt][0], gacc[mt][gt][1]);
                *(float2*)(g_glogits + (size_t)(gb + 8) * 16 + gc) =
                    make_float2(gacc[mt][gt][2], gacc[mt][gt][3]);
            }
        }
    }
}

// ---------------------------------------------------------------------------
// Softmax over experts: g_gates[t][b][e] = softmax_e(glogits[b][t*8+e] + bg)
// One thread per (b, t).
// ---------------------------------------------------------------------------
__global__ void softmax_kernel(const float* __restrict__ bg) {
    int idx = blockIdx.x * blockDim.x + threadIdx.x;   // 0 .. B*T-1
    int b = idx >> 1, t = idx & 1;
    float4 l0 = *(const float4*)(g_glogits + (size_t)b * 16 + t * 8);
    float4 l1 = *(const float4*)(g_glogits + (size_t)b * 16 + t * 8 + 4);
    float v[8] = {l0.x, l0.y, l0.z, l0.w, l1.x, l1.y, l1.z, l1.w};
    float m = -1e30f;
#pragma unroll
    for (int e = 0; e < 8; e++) { v[e] += bg[t * 8 + e]; m = fmaxf(m, v[e]); }
    float s = 0.f;
#pragma unroll
    for (int e = 0; e < 8; e++) { v[e] = expf(v[e] - m); s += v[e]; }
    float inv = 1.f / s;
    float4 o0 = make_float4(v[0] * inv, v[1] * inv, v[2] * inv, v[3] * inv);
    float4 o1 = make_float4(v[4] * inv, v[5] * inv, v[6] * inv, v[7] * inv);
    *(float4*)(g_gates + ((size_t)t * B_DIM + b) * E_DIM) = o0;
    *(float4*)(g_gates + ((size_t)t * B_DIM + b) * E_DIM + 4) = o1;
}

// ---------------------------------------------------------------------------
// GEMM2 fused with gated combine.
// CTA: 64 b-rows x 128 h2-cols; loops over all 8 experts, accumulating
// out[t][b][:] += gates[t][b][e] * relu(h[e][b]@w2t[e] + b2[e]) in registers.
// Stage (49152 B): A_hi@0 (8K) | A_lo@8K | B_hi@16K (16K) | B_lo@32K
// 8 warps = 2(m) x 4(n); warp tile 32x32 = 2x4 m16n8 tiles.
// grid = B/64, 256 threads.  smem = 2 stages + 4K gate cache.
// ---------------------------------------------------------------------------
#define G2_STAGE 49152
#define G2_SMEM  (2 * G2_STAGE + 4096)

__global__ void __launch_bounds__(256, 1)
gemm2_kernel(const float* __restrict__ b2, float* __restrict__ out) {
    extern __shared__ char sm[];
    uint32_t smb = smem_u32(sm);
    float* sgate = (float*)(sm + 2 * G2_STAGE);   // [2][64][8]
    const int b0 = blockIdx.x * 64;
    const int tid = threadIdx.x, L = tid & 31, w = tid >> 5;
    const int wm = (w >> 2) * 32, wn = (w & 3) * 32;

    // Preload this tile's gates into smem: 1024 floats, 4 per thread.
    {
        int j = tid * 4;
        int t = j >> 9, jj = j & 511;
        float4 gv = *(const float4*)(g_gates + ((size_t)t * B_DIM + b0) * E_DIM + jj);
        *(float4*)(sgate + j) = gv;
    }

    float tacc[2][2][4][4];   // [task][mt][nt][quad]
#pragma unroll
    for (int t = 0; t < 2; t++)
#pragma unroll
        for (int mt = 0; mt < 2; mt++)
#pragma unroll
            for (int nt = 0; nt < 4; nt++)
#pragma unroll
                for (int q = 0; q < 4; q++) tacc[t][mt][nt][q] = 0.f;
    float eo[2][4][4];
#pragma unroll
    for (int mt = 0; mt < 2; mt++)
#pragma unroll
        for (int nt = 0; nt < 4; nt++)
#pragma unroll
            for (int q = 0; q < 4; q++) eo[mt][nt][q] = 0.f;

    // Loader for global chunk cg (expert cg>>2, k0 = (cg&3)*64)
    auto load_cg = [&](int cg, int stage) {
        int e = cg >> 2, k0 = (cg & 3) * 64;
        const __nv_bfloat16* Ah = g_h_hi + ((size_t)e * B_DIM + b0) * H1D;
        const __nv_bfloat16* Al = g_h_lo + ((size_t)e * B_DIM + b0) * H1D;
        const __nv_bfloat16* Bh = g_w2t_hi + (size_t)e * H2D * H1D;
        const __nv_bfloat16* Bl = g_w2t_lo + (size_t)e * H2D * H1D;
        uint32_t sb = smb + (uint32_t)stage * G2_STAGE;
#pragma unroll
        for (int t = 0; t < 12; t++) {
            int j = t * 256 + tid;
            const __nv_bfloat16* p;
            uint32_t dst;
            int jj, row, c8;
            if (j < 512)       { jj = j;        p = Ah; dst = 0u; }
            else if (j < 1024) { jj = j - 512;  p = Al; dst = 8192u; }
            else if (j < 2048) { jj = j - 1024; p = Bh; dst = 16384u; }
            else               { jj = j - 2048; p = Bl; dst = 32768u; }
            row = jj >> 3; c8 = jj & 7;
            cp16(sb + dst + SWZ(row * 128 + c8 * 16),
                 p + (size_t)row * H1D + k0 + c8 * 8);
        }
        CP_COMMIT();
    };

    load_cg(0, 0);
    __syncthreads();   // also covers sgate visibility

    for (int cg = 0; cg < 32; cg++) {
        if (cg < 31) {
            load_cg(cg + 1, (cg + 1) & 1);
            asm volatile("cp.async.wait_group 1;" ::: "memory");
        } else {
            asm volatile("cp.async.wait_group 0;" ::: "memory");
        }
        __syncthreads();
        uint32_t sb = smb + (uint32_t)(cg & 1) * G2_STAGE;
#pragma unroll
        for (int ks = 0; ks < 4; ks++) {
            uint32_t afh[2][4], afl[2][4], bfh[4][2], bfl[4][2];
#pragma unroll
            for (int mt = 0; mt < 2; mt++) {
                int row = wm + mt * 16 + (L & 15);
                int co = ks * 32 + ((L >> 4) & 1) * 16;
                ldsm4(afh[mt], sb + 0u    + SWZ(row * 128 + co));
                ldsm4(afl[mt], sb + 8192u + SWZ(row * 128 + co));
            }
#pragma unroll
            for (int np = 0; np < 2; np++) {
                int g = L >> 3;
                int n = wn + np * 16 + (g >> 1) * 8 + (L & 7);
                int co = ks * 32 + (g & 1) * 16;
                uint32_t r[4];
                ldsm4(r, sb + 16384u + SWZ(n * 128 + co));
                bfh[np * 2][0] = r[0]; bfh[np * 2][1] = r[1];
                bfh[np * 2 + 1][0] = r[2]; bfh[np * 2 + 1][1] = r[3];
                ldsm4(r, sb + 32768u + SWZ(n * 128 + co));
                bfl[np * 2][0] = r[0]; bfl[np * 2][1] = r[1];
                bfl[np * 2 + 1][0] = r[2]; bfl[np * 2 + 1][1] = r[3];
            }
#pragma unroll
            for (int mt = 0; mt < 2; mt++)
#pragma unroll
                for (int nt = 0; nt < 4; nt++) {
                    mma16816(eo[mt][nt], afh[mt], bfh[nt]);
                    mma16816(eo[mt][nt], afh[mt], bfl[nt]);
                    mma16816(eo[mt][nt], afl[mt], bfh[nt]);
                }
        }
        __syncthreads();

        if ((cg & 3) == 3) {
            // Expert e complete: relu+bias, gate-weight, fold into towers.
            int e = cg >> 2;
#pragma unroll
            for (int mt = 0; mt < 2; mt++) {
                int r1 = wm + mt * 16 + (L >> 2);
                int r2 = r1 + 8;
                float g0a = sgate[(0 * 64 + r1) * 8 + e];
                float g0b = sgate[(0 * 64 + r2) * 8 + e];
                float g1a = sgate[(1 * 64 + r1) * 8 + e];
                float g1b = sgate[(1 * 64 + r2) * 8 + e];
#pragma unroll
                for (int nt = 0; nt < 4; nt++) {
                    int gc = wn + nt * 8 + 2 * (L & 3);
                    float bz0 = b2[e * H2D + gc];
                    float bz1 = b2[e * H2D + gc + 1];
                    float v00 = fmaxf(eo[mt][nt][0] + bz0, 0.f);
                    float v01 = fmaxf(eo[mt][nt][1] + bz1, 0.f);
                    float v10 = fmaxf(eo[mt][nt][2] + bz0, 0.f);
                    float v11 = fmaxf(eo[mt][nt][3] + bz1, 0.f);
                    tacc[0][mt][nt][0] += g0a * v00; tacc[0][mt][nt][1] += g0a * v01;
                    tacc[0][mt][nt][2] += g0b * v10; tacc[0][mt][nt][3] += g0b * v11;
                    tacc[1][mt][nt][0] += g1a * v00; tacc[1][mt][nt][1] += g1a * v01;
                    tacc[1][mt][nt][2] += g1b * v10; tacc[1][mt][nt][3] += g1b * v11;
                    eo[mt][nt][0] = 0.f; eo[mt][nt][1] = 0.f;
                    eo[mt][nt][2] = 0.f; eo[mt][nt][3] = 0.f;
                }
            }
        }
    }

    // Write towers: out[t][b][h2]
#pragma unroll
    for (int t = 0; t < 2; t++)
#pragma unroll
        for (int mt = 0; mt < 2; mt++) {
            int r1 = b0 + wm + mt * 16 + (L >> 2);
#pragma unroll
            for (int nt = 0; nt < 4; nt++) {
                int gc = wn + nt * 8 + 2 * (L & 3);
                *(float2*)(out + ((size_t)t * B_DIM + r1) * H2D + gc) =
                    make_float2(tacc[t][mt][nt][0], tacc[t][mt][nt][1]);
                *(float2*)(out + ((size_t)t * B_DIM + r1 + 8) * H2D + gc) =
                    make_float2(tacc[t][mt][nt][2], tacc[t][mt][nt][3]);
            }
        }
}

// ---------------------------------------------------------------------------
// Prep kernels
// ---------------------------------------------------------------------------
__global__ void split_x_kernel(const float* __restrict__ x) {
    size_t idx = (size_t)blockIdx.x * blockDim.x + threadIdx.x;
    float4 v = ((const float4*)x)[idx];
    __nv_bfloat16 h0, l0, h1, l1, h2, l2, h3, l3;
    split_bf16(v.x, h0, l0); split_bf16(v.y, h1, l1);
    split_bf16(v.z, h2, l2); split_bf16(v.w, h3, l3);
    __nv_bfloat162 ph0, ph1, pl0, pl1;
    ph0.x = h0; ph0.y = h1; ph1.x = h2; ph1.y = h3;
    pl0.x = l0; pl0.y = l1; pl1.x = l2; pl1.y = l3;
    ((__nv_bfloat162*)g_x_hi)[idx * 2 + 0] = ph0;
    ((__nv_bfloat162*)g_x_hi)[idx * 2 + 1] = ph1;
    ((__nv_bfloat162*)g_x_lo)[idx * 2 + 0] = pl0;
    ((__nv_bfloat162*)g_x_lo)[idx * 2 + 1] = pl1;
}

__global__ void prep_w1_kernel(const float* __restrict__ W1) {
    __shared__ float t[32][33];
    int e = blockIdx.z, h0 = blockIdx.x * 32, i0 = blockIdx.y * 32;
    int tx = threadIdx.x, ty = threadIdx.y;
    const float* src = W1 + (size_t)e * I_DIM * H1D;
#pragma unroll
    for (int j = 0; j < 4; j++)
        t[ty + j * 8][tx] = src[(size_t)(i0 + ty + j * 8) * H1D + h0 + tx];
    __syncthreads();
#pragma unroll
    for (int j = 0; j < 4; j++) {
        float v = t[tx][ty + j * 8];
        __nv_bfloat16 hi, lo; split_bf16(v, hi, lo);
        size_t o = ((size_t)e * H1D + h0 + ty + j * 8) * I_DIM + i0 + tx;
        g_w1t_hi[o] = hi; g_w1t_lo[o] = lo;
    }
}

__global__ void prep_w2_kernel(const float* __restrict__ W2) {
    __shared__ float t[32][33];
    int e = blockIdx.z, h2_0 = blockIdx.x * 32, h1_0 = blockIdx.y * 32;
    int tx = threadIdx.x, ty = threadIdx.y;
    const float* src = W2 + (size_t)e * H1D * H2D;
#pragma unroll
    for (int j = 0; j < 4; j++)
        t[ty + j * 8][tx] = src[(size_t)(h1_0 + ty + j * 8) * H2D + h2_0 + tx];
    __syncthreads();
#pragma unroll
    for (int j = 0; j < 4; j++) {
        float v = t[tx][ty + j * 8];
        __nv_bfloat16 hi, lo; split_bf16(v, hi, lo);
        size_t o = ((size_t)e * H2D + h2_0 + ty + j * 8) * H1D + h1_0 + tx;
        g_w2t_hi[o] = hi; g_w2t_lo[o] = lo;
    }
}

// Wg [T][I][E] -> wgt [t*8+e][I], hi/lo split.  8192 elems, 1 block.
__global__ void prep_wg_kernel(const float* __restrict__ Wg) {
    for (int idx = threadIdx.x; idx < 16 * I_DIM; idx += blockDim.x) {
        int i = idx & (I_DIM - 1), r = idx >> 9;
        int t = r >> 3, e = r & 7;
        float v = Wg[((size_t)t * I_DIM + i) * E_DIM + e];
        __nv_bfloat16 hi, lo; split_bf16(v, hi, lo);
        g_wgt_hi[(size_t)r * I_DIM + i] = hi;
        g_wgt_lo[(size_t)r * I_DIM + i] = lo;
    }
}

// ---------------------------------------------------------------------------
extern "C" void kernel_launch(void* const* d_in, const int* in_sizes, int n_in,
                              void* d_out, int out_size) {
    const float* x  = (const float*)d_in[0];
    const float* W1 = (const float*)d_in[1];
    const float* b1 = (const float*)d_in[2];
    const float* W2 = (const float*)d_in[3];
    const float* b2 = (const float*)d_in[4];
    const float* Wg = (const float*)d_in[5];
    const float* bg = (const float*)d_in[6];
    float* out = (float*)d_out;

    const int smem1 = 2 * G1_STAGE;   // 139264
    cudaFuncSetAttribute(gemm1_kernel, cudaFuncAttributeMaxDynamicSharedMemorySize, smem1);
    cudaFuncSetAttribute(gemm2_kernel, cudaFuncAttributeMaxDynamicSharedMemorySize, G2_SMEM);

    split_x_kernel<<<(B_DIM * I_DIM / 4) / 256, 256>>>(x);
    prep_w1_kernel<<<dim3(H1D / 32, I_DIM / 32, E_DIM), dim3(32, 8)>>>(W1);
    prep_w2_kernel<<<dim3(H2D / 32, H1D / 32, E_DIM), dim3(32, 8)>>>(W2);
    prep_wg_kernel<<<1, 256>>>(Wg);

    gemm1_kernel<<<dim3(B_DIM / 128, H1D / 128, E_DIM), 256, smem1>>>(b1);
    softmax_kernel<<<(B_DIM * T_DIM) / 256, 256>>>(bg);
    gemm2_kernel<<<B_DIM / 64, 256, G2_SMEM>>>(b2, out);
}

// round 11
// speedup vs baseline: 3.3144x; 1.0225x over previous
#include <cuda_runtime.h>
#include <cuda_bf16.h>
#include <cstdint>

// Problem constants
#define B_DIM 16384
#define I_DIM 512
#define H1D   256
#define H2D   128
#define E_DIM 8
#define T_DIM 2

// ---------------------------------------------------------------------------
// Device globals (allocation-free scratch)
// ---------------------------------------------------------------------------
__device__ __nv_bfloat16 g_x_hi[(size_t)B_DIM * I_DIM];
__device__ __nv_bfloat16 g_x_lo[(size_t)B_DIM * I_DIM];
__device__ __nv_bfloat16 g_w1t_hi[(size_t)E_DIM * H1D * I_DIM];   // [E][H1][I]
__device__ __nv_bfloat16 g_w1t_lo[(size_t)E_DIM * H1D * I_DIM];
__device__ __nv_bfloat16 g_w2t_hi[(size_t)E_DIM * H2D * H1D];     // [E][H2][H1]
__device__ __nv_bfloat16 g_w2t_lo[(size_t)E_DIM * H2D * H1D];
__device__ __nv_bfloat16 g_wgt_hi[16 * I_DIM];                    // [t*8+e][I]
__device__ __nv_bfloat16 g_wgt_lo[16 * I_DIM];
__device__ __nv_bfloat16 g_h_hi[(size_t)E_DIM * B_DIM * H1D];     // [E][B][H1]
__device__ __nv_bfloat16 g_h_lo[(size_t)E_DIM * B_DIM * H1D];
__device__ float         g_glogits[(size_t)B_DIM * 16];           // [B][t*8+e]

// ---------------------------------------------------------------------------
// Helpers (sm_80+ only — environment compiles virtual compute_103, which
// rejects all tcgen05/sm_103a-suffix instructions)
// ---------------------------------------------------------------------------
__device__ __forceinline__ uint32_t smem_u32(const void* p) {
    uint32_t a;
    asm("{ .reg .u64 t; cvta.to.shared.u64 t, %1; cvt.u32.u64 %0, t; }"
        : "=r"(a) : "l"(p));
    return a;
}

// 128B-period XOR swizzle
#define SWZ(o) ((uint32_t)(o) ^ ((((uint32_t)(o)) >> 3) & 0x70u))

__device__ __forceinline__ void cp16(uint32_t s, const void* g) {
    asm volatile("cp.async.cg.shared.global [%0], [%1], 16;"
                 :: "r"(s), "l"(__cvta_generic_to_global(g)));
}
#define CP_COMMIT() asm volatile("cp.async.commit_group;" ::: "memory")
#define CP_WAIT0()  asm volatile("cp.async.wait_group 0;" ::: "memory")
#define CP_WAIT1()  asm volatile("cp.async.wait_group 1;" ::: "memory")

__device__ __forceinline__ void ldsm4(uint32_t* r, uint32_t addr) {
    asm volatile("ldmatrix.sync.aligned.m8n8.x4.shared.b16 {%0,%1,%2,%3}, [%4];"
                 : "=r"(r[0]), "=r"(r[1]), "=r"(r[2]), "=r"(r[3]) : "r"(addr));
}

__device__ __forceinline__ void mma16816(float* d, const uint32_t* a, const uint32_t* b) {
    asm volatile("mma.sync.aligned.m16n8k16.row.col.f32.bf16.bf16.f32 "
                 "{%0,%1,%2,%3}, {%4,%5,%6,%7}, {%8,%9}, {%0,%1,%2,%3};"
                 : "+f"(d[0]), "+f"(d[1]), "+f"(d[2]), "+f"(d[3])
                 : "r"(a[0]), "r"(a[1]), "r"(a[2]), "r"(a[3]), "r"(b[0]), "r"(b[1]));
}

__device__ __forceinline__ void split_bf16(float v, __nv_bfloat16& hi, __nv_bfloat16& lo) {
    hi = __float2bfloat16(v);
    lo = __float2bfloat16(v - __bfloat162float(hi));
}

// ---------------------------------------------------------------------------
// GEMM1 stage layout (69632 B):
//   A_hi @0 (16K) | A_lo @16K | B_hi @32K | B_lo @48K | Wg_hi @64K (2K) | Wg_lo @66K
// Tiles: A 128x64, B 128x64, Wg 16x64; pitch 128B, swizzled.
// 3 stages, 1 sync per chunk, 2-chunk prefetch.
// Warp grid: 8 warps = 4(m) x 2(n); warp tile 32x64 = 2x8 m16n8 tiles.
// ---------------------------------------------------------------------------
#define G1_STAGE 69632
#define G1_SMEM  (3 * G1_STAGE)

__device__ __forceinline__ void gemm1_compute(uint32_t sb, int wm, int wn, int L,
                                              float acc[2][8][4],
                                              bool gate, float gacc[2][2][4]) {
#pragma unroll
    for (int ks = 0; ks < 4; ks++) {
        uint32_t afh[2][4], afl[2][4], bfh[8][2], bfl[8][2];
#pragma unroll
        for (int mt = 0; mt < 2; mt++) {
            int row = wm + mt * 16 + (L & 15);
            int co = ks * 32 + ((L >> 4) & 1) * 16;
            ldsm4(afh[mt], sb + 0u     + SWZ(row * 128 + co));
            ldsm4(afl[mt], sb + 16384u + SWZ(row * 128 + co));
        }
#pragma unroll
        for (int np = 0; np < 4; np++) {
            int g = L >> 3;
            int n = wn + np * 16 + (g >> 1) * 8 + (L & 7);
            int co = ks * 32 + (g & 1) * 16;
            uint32_t r[4];
            ldsm4(r, sb + 32768u + SWZ(n * 128 + co));
            bfh[np * 2][0] = r[0]; bfh[np * 2][1] = r[1];
            bfh[np * 2 + 1][0] = r[2]; bfh[np * 2 + 1][1] = r[3];
            ldsm4(r, sb + 49152u + SWZ(n * 128 + co));
            bfl[np * 2][0] = r[0]; bfl[np * 2][1] = r[1];
            bfl[np * 2 + 1][0] = r[2]; bfl[np * 2 + 1][1] = r[3];
        }
#pragma unroll
        for (int mt = 0; mt < 2; mt++)
#pragma unroll
            for (int nt = 0; nt < 8; nt++) {
                mma16816(acc[mt][nt], afh[mt], bfh[nt]);
                mma16816(acc[mt][nt], afh[mt], bfl[nt]);
                mma16816(acc[mt][nt], afl[mt], bfh[nt]);
            }
        if (gate) {
            int g = L >> 3;
            int n = (g >> 1) * 8 + (L & 7);
            int co = ks * 32 + (g & 1) * 16;
            uint32_t rh[4], rl[4];
            ldsm4(rh, sb + 65536u + SWZ(n * 128 + co));
            ldsm4(rl, sb + 67584u + SWZ(n * 128 + co));
            uint32_t gbh[2][2] = {{rh[0], rh[1]}, {rh[2], rh[3]}};
            uint32_t gbl[2][2] = {{rl[0], rl[1]}, {rl[2], rl[3]}};
#pragma unroll
            for (int mt = 0; mt < 2; mt++)
#pragma unroll
                for (int gt = 0; gt < 2; gt++) {
                    mma16816(gacc[mt][gt], afh[mt], gbh[gt]);
                    mma16816(gacc[mt][gt], afh[mt], gbl[gt]);
                    mma16816(gacc[mt][gt], afl[mt], gbh[gt]);
                }
        }
    }
}

__device__ __forceinline__ void gemm1_load(uint32_t smb, int stage, int tid, int k0,
                                           const __nv_bfloat16* Ah, const __nv_bfloat16* Al,
                                           const __nv_bfloat16* Bh, const __nv_bfloat16* Bl,
                                           bool gate) {
    uint32_t sb = smb + (uint32_t)stage * G1_STAGE;
#pragma unroll
    for (int t = 0; t < 16; t++) {
        const int mat = t >> 2;
        const __nv_bfloat16* p = (mat == 0) ? Ah : (mat == 1) ? Al : (mat == 2) ? Bh : Bl;
        int j = (t & 3) * 256 + tid;
        int row = j >> 3, c8 = j & 7;
        cp16(sb + (uint32_t)mat * 16384u + SWZ(row * 128 + c8 * 16),
             p + (size_t)row * I_DIM + k0 + c8 * 8);
    }
    if (gate) {
        int mat = tid >> 7, jj = tid & 127;
        int row = jj >> 3, c8 = jj & 7;
        const __nv_bfloat16* p = mat ? g_wgt_lo : g_wgt_hi;
        cp16(sb + 65536u + (uint32_t)mat * 2048u + SWZ(row * 128 + c8 * 16),
             p + (size_t)row * I_DIM + k0 + c8 * 8);
    }
    CP_COMMIT();
}

// ---------------------------------------------------------------------------
// GEMM1: C[b][h1] = x[b][:] . w1t[h1][:]  (per expert), +b1, relu,
// split -> g_h_hi/g_h_lo.  Gate CTAs (n0==0,e==0) also emit x@Wg^T logits.
// grid = (B/128, H1/128, E), 256 threads.
// ---------------------------------------------------------------------------
__global__ void __launch_bounds__(256, 1)
gemm1_kernel(const float* __restrict__ b1) {
    extern __shared__ char sm[];
    uint32_t smb = smem_u32(sm);
    const int e = blockIdx.z, b0 = blockIdx.x * 128, n0 = blockIdx.y * 128;
    const int tid = threadIdx.x, L = tid & 31, w = tid >> 5;
    const int wm = (w >> 1) * 32, wn = (w & 1) * 64;
    const bool gate = (blockIdx.y == 0) && (blockIdx.z == 0);

    const __nv_bfloat16* Ah = g_x_hi + (size_t)b0 * I_DIM;
    const __nv_bfloat16* Al = g_x_lo + (size_t)b0 * I_DIM;
    const __nv_bfloat16* Bh = g_w1t_hi + ((size_t)e * H1D + n0) * I_DIM;
    const __nv_bfloat16* Bl = g_w1t_lo + ((size_t)e * H1D + n0) * I_DIM;

    float acc[2][8][4];
    float gacc[2][2][4];
#pragma unroll
    for (int mt = 0; mt < 2; mt++) {
#pragma unroll
        for (int nt = 0; nt < 8; nt++)
#pragma unroll
            for (int q = 0; q < 4; q++) acc[mt][nt][q] = 0.f;
#pragma unroll
        for (int gt = 0; gt < 2; gt++)
#pragma unroll
            for (int q = 0; q < 4; q++) gacc[mt][gt][q] = 0.f;
    }

    // Prologue: prefetch chunks 0 and 1 into stages 0 and 1.
    gemm1_load(smb, 0, tid, 0, Ah, Al, Bh, Bl, gate);
    gemm1_load(smb, 1, tid, 64, Ah, Al, Bh, Bl, gate);

    // Mainloop: 3-stage rotation, one sync per chunk.
#pragma unroll
    for (int c = 0; c < 8; c++) {
        if (c < 7) { CP_WAIT1(); } else { CP_WAIT0(); }
        __syncthreads();
        if (c + 2 < 8)
            gemm1_load(smb, (c + 2) % 3, tid, (c + 2) * 64, Ah, Al, Bh, Bl, gate);
        gemm1_compute(smb + (uint32_t)(c % 3) * G1_STAGE, wm, wn, L, acc, gate, gacc);
    }

    // Epilogue: bias + relu + hi/lo split -> g_h
    float bias[8][2];
#pragma unroll
    for (int nt = 0; nt < 8; nt++) {
        int gn = n0 + wn + nt * 8 + 2 * (L & 3);
        bias[nt][0] = b1[e * H1D + gn];
        bias[nt][1] = b1[e * H1D + gn + 1];
    }
#pragma unroll
    for (int mt = 0; mt < 2; mt++) {
        int gb = b0 + wm + mt * 16 + (L >> 2);
#pragma unroll
        for (int nt = 0; nt < 8; nt++) {
            int gn = n0 + wn + nt * 8 + 2 * (L & 3);
            float v00 = fmaxf(acc[mt][nt][0] + bias[nt][0], 0.f);
            float v01 = fmaxf(acc[mt][nt][1] + bias[nt][1], 0.f);
            float v10 = fmaxf(acc[mt][nt][2] + bias[nt][0], 0.f);
            float v11 = fmaxf(acc[mt][nt][3] + bias[nt][1], 0.f);
            __nv_bfloat16 h00, l00, h01, l01, h10, l10, h11, l11;
            split_bf16(v00, h00, l00); split_bf16(v01, h01, l01);
            split_bf16(v10, h10, l10); split_bf16(v11, h11, l11);
            size_t o0 = ((size_t)e * B_DIM + gb) * H1D + gn;
            size_t o1 = o0 + (size_t)8 * H1D;
            __nv_bfloat162 ph0; ph0.x = h00; ph0.y = h01;
            __nv_bfloat162 pl0; pl0.x = l00; pl0.y = l01;
            __nv_bfloat162 ph1; ph1.x = h10; ph1.y = h11;
            __nv_bfloat162 pl1; pl1.x = l10; pl1.y = l11;
            *(__nv_bfloat162*)(g_h_hi + o0) = ph0;
            *(__nv_bfloat162*)(g_h_lo + o0) = pl0;
            *(__nv_bfloat162*)(g_h_hi + o1) = ph1;
            *(__nv_bfloat162*)(g_h_lo + o1) = pl1;
        }
    }
    if (gate) {
#pragma unroll
        for (int mt = 0; mt < 2; mt++) {
            int gb = b0 + wm + mt * 16 + (L >> 2);
#pragma unroll
            for (int gt = 0; gt < 2; gt++) {
                int gc = gt * 8 + 2 * (L & 3);
                *(float2*)(g_glogits + (size_t)gb * 16 + gc) =
                    make_float2(gacc[mt][gt][0], gacc[mt][gt][1]);
                *(float2*)(g_glogits + (size_t)(gb + 8) * 16 + gc) =
                    make_float2(gacc[mt][gt][2], gacc[mt][gt][3]);
            }
        }
    }
}

// ---------------------------------------------------------------------------
// GEMM2 fused with softmax + gated combine.
// CTA: 64 b-rows x 128 h2-cols; loops over all 8 experts (32 K-chunks),
// accumulating out[t][b][:] += softmax_e(logits)[t][b][e] * relu(h@w2t + b2).
// Stage (49152 B): A_hi@0 (8K) | A_lo@8K | B_hi@16K (16K) | B_lo@32K
// 3 stages + 4K gate cache.  8 warps = 2(m) x 4(n); warp tile 32x32.
// grid = B/64, 256 threads.
// ---------------------------------------------------------------------------
#define G2_STAGE 49152
#define G2_SMEM  (3 * G2_STAGE + 4096)

__device__ __forceinline__ void gemm2_load(uint32_t smb, int stage, int tid,
                                           int b0, int cg) {
    int e = cg >> 2, k0 = (cg & 3) * 64;
    const __nv_bfloat16* Ah = g_h_hi + ((size_t)e * B_DIM + b0) * H1D;
    const __nv_bfloat16* Al = g_h_lo + ((size_t)e * B_DIM + b0) * H1D;
    const __nv_bfloat16* Bh = g_w2t_hi + (size_t)e * H2D * H1D;
    const __nv_bfloat16* Bl = g_w2t_lo + (size_t)e * H2D * H1D;
    uint32_t sb = smb + (uint32_t)stage * G2_STAGE;
#pragma unroll
    for (int t = 0; t < 12; t++) {
        int j = t * 256 + tid;
        const __nv_bfloat16* p;
        uint32_t dst;
        int jj;
        if (j < 512)       { jj = j;        p = Ah; dst = 0u; }
        else if (j < 1024) { jj = j - 512;  p = Al; dst = 8192u; }
        else if (j < 2048) { jj = j - 1024; p = Bh; dst = 16384u; }
        else               { jj = j - 2048; p = Bl; dst = 32768u; }
        int row = jj >> 3, c8 = jj & 7;
        cp16(sb + dst + SWZ(row * 128 + c8 * 16),
             p + (size_t)row * H1D + k0 + c8 * 8);
    }
    CP_COMMIT();
}

__global__ void __launch_bounds__(256, 1)
gemm2_kernel(const float* __restrict__ b2, const float* __restrict__ bg,
             float* __restrict__ out) {
    extern __shared__ char sm[];
    uint32_t smb = smem_u32(sm);
    float* sgate = (float*)(sm + 3 * G2_STAGE);   // [2][64][8]
    const int b0 = blockIdx.x * 64;
    const int tid = threadIdx.x, L = tid & 31, w = tid >> 5;
    const int wm = (w >> 2) * 32, wn = (w & 3) * 32;

    // Prologue: prefetch chunks 0, 1.
    gemm2_load(smb, 0, tid, b0, 0);
    gemm2_load(smb, 1, tid, b0, 1);

    // Fused softmax: threads 0..127 each handle one (row, task).
    if (tid < 128) {
        int r = tid >> 1, t = tid & 1;
        int b = b0 + r;
        float4 l0 = *(const float4*)(g_glogits + (size_t)b * 16 + t * 8);
        float4 l1 = *(const float4*)(g_glogits + (size_t)b * 16 + t * 8 + 4);
        float v[8] = {l0.x, l0.y, l0.z, l0.w, l1.x, l1.y, l1.z, l1.w};
        float m = -1e30f;
#pragma unroll
        for (int e2 = 0; e2 < 8; e2++) { v[e2] += bg[t * 8 + e2]; m = fmaxf(m, v[e2]); }
        float s = 0.f;
#pragma unroll
        for (int e2 = 0; e2 < 8; e2++) { v[e2] = expf(v[e2] - m); s += v[e2]; }
        float inv = 1.f / s;
#pragma unroll
        for (int e2 = 0; e2 < 8; e2++)
            sgate[(t * 64 + r) * 8 + e2] = v[e2] * inv;
    }

    float tacc[2][2][4][4];   // [task][mt][nt][quad]
#pragma unroll
    for (int t = 0; t < 2; t++)
#pragma unroll
        for (int mt = 0; mt < 2; mt++)
#pragma unroll
            for (int nt = 0; nt < 4; nt++)
#pragma unroll
                for (int q = 0; q < 4; q++) tacc[t][mt][nt][q] = 0.f;
    float eo[2][4][4];
#pragma unroll
    for (int mt = 0; mt < 2; mt++)
#pragma unroll
        for (int nt = 0; nt < 4; nt++)
#pragma unroll
            for (int q = 0; q < 4; q++) eo[mt][nt][q] = 0.f;

    int s_load = 2, s_comp = 0;
    for (int cg = 0; cg < 32; cg++) {
        if (cg < 31) { CP_WAIT1(); } else { CP_WAIT0(); }
        __syncthreads();
        if (cg + 2 < 32) {
            gemm2_load(smb, s_load, tid, b0, cg + 2);
            if (++s_load == 3) s_load = 0;
        }
        uint32_t sb = smb + (uint32_t)s_comp * G2_STAGE;
        if (++s_comp == 3) s_comp = 0;
#pragma unroll
        for (int ks = 0; ks < 4; ks++) {
            uint32_t afh[2][4], afl[2][4], bfh[4][2], bfl[4][2];
#pragma unroll
            for (int mt = 0; mt < 2; mt++) {
                int row = wm + mt * 16 + (L & 15);
                int co = ks * 32 + ((L >> 4) & 1) * 16;
                ldsm4(afh[mt], sb + 0u    + SWZ(row * 128 + co));
                ldsm4(afl[mt], sb + 8192u + SWZ(row * 128 + co));
            }
#pragma unroll
            for (int np = 0; np < 2; np++) {
                int g = L >> 3;
                int n = wn + np * 16 + (g >> 1) * 8 + (L & 7);
                int co = ks * 32 + (g & 1) * 16;
                uint32_t r[4];
                ldsm4(r, sb + 16384u + SWZ(n * 128 + co));
                bfh[np * 2][0] = r[0]; bfh[np * 2][1] = r[1];
                bfh[np * 2 + 1][0] = r[2]; bfh[np * 2 + 1][1] = r[3];
                ldsm4(r, sb + 32768u + SWZ(n * 128 + co));
                bfl[np * 2][0] = r[0]; bfl[np * 2][1] = r[1];
                bfl[np * 2 + 1][0] = r[2]; bfl[np * 2 + 1][1] = r[3];
            }
#pragma unroll
            for (int mt = 0; mt < 2; mt++)
#pragma unroll
                for (int nt = 0; nt < 4; nt++) {
                    mma16816(eo[mt][nt], afh[mt], bfh[nt]);
                    mma16816(eo[mt][nt], afh[mt], bfl[nt]);
                    mma16816(eo[mt][nt], afl[mt], bfh[nt]);
                }
        }

        if ((cg & 3) == 3) {
            // Expert complete: relu+bias, gate-weight, fold into towers.
            int e = cg >> 2;
#pragma unroll
            for (int mt = 0; mt < 2; mt++) {
                int r1 = wm + mt * 16 + (L >> 2);
                int r2 = r1 + 8;
                float g0a = sgate[(0 * 64 + r1) * 8 + e];
                float g0b = sgate[(0 * 64 + r2) * 8 + e];
                float g1a = sgate[(1 * 64 + r1) * 8 + e];
                float g1b = sgate[(1 * 64 + r2) * 8 + e];
#pragma unroll
                for (int nt = 0; nt < 4; nt++) {
                    int gc = wn + nt * 8 + 2 * (L & 3);
                    float bz0 = b2[e * H2D + gc];
                    float bz1 = b2[e * H2D + gc + 1];
                    float v00 = fmaxf(eo[mt][nt][0] + bz0, 0.f);
                    float v01 = fmaxf(eo[mt][nt][1] + bz1, 0.f);
                    float v10 = fmaxf(eo[mt][nt][2] + bz0, 0.f);
                    float v11 = fmaxf(eo[mt][nt][3] + bz1, 0.f);
                    tacc[0][mt][nt][0] += g0a * v00; tacc[0][mt][nt][1] += g0a * v01;
                    tacc[0][mt][nt][2] += g0b * v10; tacc[0][mt][nt][3] += g0b * v11;
                    tacc[1][mt][nt][0] += g1a * v00; tacc[1][mt][nt][1] += g1a * v01;
                    tacc[1][mt][nt][2] += g1b * v10; tacc[1][mt][nt][3] += g1b * v11;
                    eo[mt][nt][0] = 0.f; eo[mt][nt][1] = 0.f;
                    eo[mt][nt][2] = 0.f; eo[mt][nt][3] = 0.f;
                }
            }
        }
    }

    // Write towers: out[t][b][h2]
#pragma unroll
    for (int t = 0; t < 2; t++)
#pragma unroll
        for (int mt = 0; mt < 2; mt++) {
            int r1 = b0 + wm + mt * 16 + (L >> 2);
#pragma unroll
            for (int nt = 0; nt < 4; nt++) {
                int gc = wn + nt * 8 + 2 * (L & 3);
                *(float2*)(out + ((size_t)t * B_DIM + r1) * H2D + gc) =
                    make_float2(tacc[t][mt][nt][0], tacc[t][mt][nt][1]);
                *(float2*)(out + ((size_t)t * B_DIM + r1 + 8) * H2D + gc) =
                    make_float2(tacc[t][mt][nt][2], tacc[t][mt][nt][3]);
            }
        }
}

// ---------------------------------------------------------------------------
// Prep kernels
// ---------------------------------------------------------------------------
__global__ void split_x_kernel(const float* __restrict__ x) {
    size_t idx = (size_t)blockIdx.x * blockDim.x + threadIdx.x;
    float4 v = ((const float4*)x)[idx];
    __nv_bfloat16 h0, l0, h1, l1, h2, l2, h3, l3;
    split_bf16(v.x, h0, l0); split_bf16(v.y, h1, l1);
    split_bf16(v.z, h2, l2); split_bf16(v.w, h3, l3);
    __nv_bfloat162 ph0, ph1, pl0, pl1;
    ph0.x = h0; ph0.y = h1; ph1.x = h2; ph1.y = h3;
    pl0.x = l0; pl0.y = l1; pl1.x = l2; pl1.y = l3;
    ((__nv_bfloat162*)g_x_hi)[idx * 2 + 0] = ph0;
    ((__nv_bfloat162*)g_x_hi)[idx * 2 + 1] = ph1;
    ((__nv_bfloat162*)g_x_lo)[idx * 2 + 0] = pl0;
    ((__nv_bfloat162*)g_x_lo)[idx * 2 + 1] = pl1;
}

__global__ void prep_w1_kernel(const float* __restrict__ W1) {
    __shared__ float t[32][33];
    int e = blockIdx.z, h0 = blockIdx.x * 32, i0 = blockIdx.y * 32;
    int tx = threadIdx.x, ty = threadIdx.y;
    const float* src = W1 + (size_t)e * I_DIM * H1D;
#pragma unroll
    for (int j = 0; j < 4; j++)
        t[ty + j * 8][tx] = src[(size_t)(i0 + ty + j * 8) * H1D + h0 + tx];
    __syncthreads();
#pragma unroll
    for (int j = 0; j < 4; j++) {
        float v = t[tx][ty + j * 8];
        __nv_bfloat16 hi, lo; split_bf16(v, hi, lo);
        size_t o = ((size_t)e * H1D + h0 + ty + j * 8) * I_DIM + i0 + tx;
        g_w1t_hi[o] = hi; g_w1t_lo[o] = lo;
    }
}

__global__ void prep_w2_kernel(const float* __restrict__ W2) {
    __shared__ float t[32][33];
    int e = blockIdx.z, h2_0 = blockIdx.x * 32, h1_0 = blockIdx.y * 32;
    int tx = threadIdx.x, ty = threadIdx.y;
    const float* src = W2 + (size_t)e * H1D * H2D;
#pragma unroll
    for (int j = 0; j < 4; j++)
        t[ty + j * 8][tx] = src[(size_t)(h1_0 + ty + j * 8) * H2D + h2_0 + tx];
    __syncthreads();
#pragma unroll
    for (int j = 0; j < 4; j++) {
        float v = t[tx][ty + j * 8];
        __nv_bfloat16 hi, lo; split_bf16(v, hi, lo);
        size_t o = ((size_t)e * H2D + h2_0 + ty + j * 8) * H1D + h1_0 + tx;
        g_w2t_hi[o] = hi; g_w2t_lo[o] = lo;
    }
}

// Wg [T][I][E] -> wgt [t*8+e][I], hi/lo split.  8192 elems, 16 blocks.
__global__ void prep_wg_kernel(const float* __restrict__ Wg) {
    int idx = blockIdx.x * blockDim.x + threadIdx.x;
    if (idx >= 16 * I_DIM) return;
    int i = idx & (I_DIM - 1), r = idx >> 9;
    int t = r >> 3, e = r & 7;
    float v = Wg[((size_t)t * I_DIM + i) * E_DIM + e];
    __nv_bfloat16 hi, lo; split_bf16(v, hi, lo);
    g_wgt_hi[(size_t)r * I_DIM + i] = hi;
    g_wgt_lo[(size_t)r * I_DIM + i] = lo;
}

// ---------------------------------------------------------------------------
extern "C" void kernel_launch(void* const* d_in, const int* in_sizes, int n_in,
                              void* d_out, int out_size) {
    const float* x  = (const float*)d_in[0];
    const float* W1 = (const float*)d_in[1];
    const float* b1 = (const float*)d_in[2];
    const float* W2 = (const float*)d_in[3];
    const float* b2 = (const float*)d_in[4];
    const float* Wg = (const float*)d_in[5];
    const float* bg = (const float*)d_in[6];
    float* out = (float*)d_out;

    cudaFuncSetAttribute(gemm1_kernel, cudaFuncAttributeMaxDynamicSharedMemorySize, G1_SMEM);
    cudaFuncSetAttribute(gemm2_kernel, cudaFuncAttributeMaxDynamicSharedMemorySize, G2_SMEM);

    split_x_kernel<<<(B_DIM * I_DIM / 4) / 256, 256>>>(x);
    prep_w1_kernel<<<dim3(H1D / 32, I_DIM / 32, E_DIM), dim3(32, 8)>>>(W1);
    prep_w2_kernel<<<dim3(H2D / 32, H1D / 32, E_DIM), dim3(32, 8)>>>(W2);
    prep_wg_kernel<<<(16 * I_DIM) / 256, 256>>>(Wg);

    gemm1_kernel<<<dim3(B_DIM / 128, H1D / 128, E_DIM), 256, G1_SMEM>>>(b1);
    gemm2_kernel<<<B_DIM / 64, 256, G2_SMEM>>>(b2, bg, out);
}

// round 15
// speedup vs baseline: 4.4162x; 1.3324x over previous
#include <cuda_runtime.h>
#include <cuda_fp16.h>
#include <cstdint>

// Problem constants
#define B_DIM 16384
#define I_DIM 512
#define H1D   256
#define H2D   128
#define E_DIM 8
#define T_DIM 2

// ---------------------------------------------------------------------------
// Device globals (allocation-free scratch) — fp16 numerics:
// A-side operands (x, h) split hi/lo fp16; weights single fp16.
// ---------------------------------------------------------------------------
__device__ __half g_x_hi[(size_t)B_DIM * I_DIM];
__device__ __half g_x_lo[(size_t)B_DIM * I_DIM];
__device__ __half g_w1t[(size_t)E_DIM * H1D * I_DIM];   // [E][H1][I]
__device__ __half g_w2t[(size_t)E_DIM * H2D * H1D];     // [E][H2][H1]
__device__ __half g_wgt[16 * I_DIM];                    // [t*8+e][I]
__device__ __half g_h_hi[(size_t)E_DIM * B_DIM * H1D];  // [E][B][H1]
__device__ __half g_h_lo[(size_t)E_DIM * B_DIM * H1D];
__device__ float  g_glogits[(size_t)B_DIM * 16];        // [B][t*8+e]

// ---------------------------------------------------------------------------
// Helpers (sm_80+ only — environment compiles virtual compute_103, which
// rejects all tcgen05/sm_103a-suffix instructions)
// ---------------------------------------------------------------------------
__device__ __forceinline__ uint32_t smem_u32(const void* p) {
    uint32_t a;
    asm("{ .reg .u64 t; cvta.to.shared.u64 t, %1; cvt.u32.u64 %0, t; }"
        : "=r"(a) : "l"(p));
    return a;
}

// 128B-period XOR swizzle
#define SWZ(o) ((uint32_t)(o) ^ ((((uint32_t)(o)) >> 3) & 0x70u))

__device__ __forceinline__ void cp16(uint32_t s, const void* g) {
    asm volatile("cp.async.cg.shared.global [%0], [%1], 16;"
                 :: "r"(s), "l"(__cvta_generic_to_global(g)));
}
#define CP_COMMIT() asm volatile("cp.async.commit_group;" ::: "memory")
#define CP_WAIT2()  asm volatile("cp.async.wait_group 2;" ::: "memory")

__device__ __forceinline__ void ldsm4(uint32_t* r, uint32_t addr) {
    asm volatile("ldmatrix.sync.aligned.m8n8.x4.shared.b16 {%0,%1,%2,%3}, [%4];"
                 : "=r"(r[0]), "=r"(r[1]), "=r"(r[2]), "=r"(r[3]) : "r"(addr));
}

__device__ __forceinline__ void mma16816(float* d, const uint32_t* a, const uint32_t* b) {
    asm volatile("mma.sync.aligned.m16n8k16.row.col.f32.f16.f16.f32 "
                 "{%0,%1,%2,%3}, {%4,%5,%6,%7}, {%8,%9}, {%0,%1,%2,%3};"
                 : "+f"(d[0]), "+f"(d[1]), "+f"(d[2]), "+f"(d[3])
                 : "r"(a[0]), "r"(a[1]), "r"(a[2]), "r"(a[3]), "r"(b[0]), "r"(b[1]));
}

__device__ __forceinline__ void split_f16(float v, __half& hi, __half& lo) {
    hi = __float2half_rn(v);
    lo = __float2half_rn(v - __half2float(hi));
}

// ---------------------------------------------------------------------------
// GEMM1 stage layout (51200 B):
//   A_hi @0 (16K) | A_lo @16K (16K) | B @32K (16K) | Wg @48K (2K)
// Tiles: A 128x64 fp16, B 128x64, Wg 16x64; pitch 128B, swizzled.
// 4 stages, always-commit, wait_group 2 (3-chunk prefetch depth).
// Warp grid: 8 warps = 4(m) x 2(n); warp tile 32x64 = 2x8 m16n8 tiles.
// 2 MMAs per (mt,nt,ks): ah*b + al*b.
// ---------------------------------------------------------------------------
#define G1_STAGE 51200
#define G1_SMEM  (4 * G1_STAGE)

__device__ __forceinline__ void gemm1_compute(uint32_t sb, int wm, int wn, int L,
                                              float acc[2][8][4],
                                              bool gate, float gacc[2][2][4]) {
#pragma unroll
    for (int ks = 0; ks < 4; ks++) {
        uint32_t afh[2][4], afl[2][4], bf[8][2];
#pragma unroll
        for (int mt = 0; mt < 2; mt++) {
            int row = wm + mt * 16 + (L & 15);
            int co = ks * 32 + ((L >> 4) & 1) * 16;
            ldsm4(afh[mt], sb + 0u     + SWZ(row * 128 + co));
            ldsm4(afl[mt], sb + 16384u + SWZ(row * 128 + co));
        }
#pragma unroll
        for (int np = 0; np < 4; np++) {
            int g = L >> 3;
            int n = wn + np * 16 + (g >> 1) * 8 + (L & 7);
            int co = ks * 32 + (g & 1) * 16;
            uint32_t r[4];
            ldsm4(r, sb + 32768u + SWZ(n * 128 + co));
            bf[np * 2][0] = r[0]; bf[np * 2][1] = r[1];
            bf[np * 2 + 1][0] = r[2]; bf[np * 2 + 1][1] = r[3];
        }
#pragma unroll
        for (int mt = 0; mt < 2; mt++)
#pragma unroll
            for (int nt = 0; nt < 8; nt++) {
                mma16816(acc[mt][nt], afh[mt], bf[nt]);
                mma16816(acc[mt][nt], afl[mt], bf[nt]);
            }
        if (gate) {
            int g = L >> 3;
            int n = (g >> 1) * 8 + (L & 7);
            int co = ks * 32 + (g & 1) * 16;
            uint32_t rg[4];
            ldsm4(rg, sb + 49152u + SWZ(n * 128 + co));
            uint32_t gb[2][2] = {{rg[0], rg[1]}, {rg[2], rg[3]}};
#pragma unroll
            for (int mt = 0; mt < 2; mt++)
#pragma unroll
                for (int gt = 0; gt < 2; gt++) {
                    mma16816(gacc[mt][gt], afh[mt], gb[gt]);
                    mma16816(gacc[mt][gt], afl[mt], gb[gt]);
                }
        }
    }
}

__device__ __forceinline__ void gemm1_load(uint32_t smb, int stage, int tid, int k0,
                                           const __half* Ah, const __half* Al,
                                           const __half* Bw, bool gate) {
    uint32_t sb = smb + (uint32_t)stage * G1_STAGE;
#pragma unroll
    for (int t = 0; t < 12; t++) {
        const int mat = t >> 2;   // 0..2
        const __half* p = (mat == 0) ? Ah : (mat == 1) ? Al : Bw;
        int j = (t & 3) * 256 + tid;
        int row = j >> 3, c8 = j & 7;
        cp16(sb + (uint32_t)mat * 16384u + SWZ(row * 128 + c8 * 16),
             p + (size_t)row * I_DIM + k0 + c8 * 8);
    }
    if (gate && tid < 128) {
        int row = tid >> 3, c8 = tid & 7;
        cp16(sb + 49152u + SWZ(row * 128 + c8 * 16),
             g_wgt + (size_t)row * I_DIM + k0 + c8 * 8);
    }
    CP_COMMIT();
}

// ---------------------------------------------------------------------------
// GEMM1: C[b][h1] = x[b][:] . w1t[h1][:]  (per expert), +b1, relu,
// split -> g_h_hi/g_h_lo.  Gate CTAs (n0==0,e==0) also emit x@Wg^T logits.
// grid = (B/128, H1/128, E), 256 threads.
// ---------------------------------------------------------------------------
__global__ void __launch_bounds__(256, 1)
gemm1_kernel(const float* __restrict__ b1) {
    extern __shared__ char sm[];
    uint32_t smb = smem_u32(sm);
    const int e = blockIdx.z, b0 = blockIdx.x * 128, n0 = blockIdx.y * 128;
    const int tid = threadIdx.x, L = tid & 31, w = tid >> 5;
    const int wm = (w >> 1) * 32, wn = (w & 1) * 64;
    const bool gate = (blockIdx.y == 0) && (blockIdx.z == 0);

    const __half* Ah = g_x_hi + (size_t)b0 * I_DIM;
    const __half* Al = g_x_lo + (size_t)b0 * I_DIM;
    const __half* Bw = g_w1t + ((size_t)e * H1D + n0) * I_DIM;

    float acc[2][8][4];
    float gacc[2][2][4];
#pragma unroll
    for (int mt = 0; mt < 2; mt++) {
#pragma unroll
        for (int nt = 0; nt < 8; nt++)
#pragma unroll
            for (int q = 0; q < 4; q++) acc[mt][nt][q] = 0.f;
#pragma unroll
        for (int gt = 0; gt < 2; gt++)
#pragma unroll
            for (int q = 0; q < 4; q++) gacc[mt][gt][q] = 0.f;
    }

    // Prologue: prefetch chunks 0..2 into stages 0..2.
    gemm1_load(smb, 0, tid, 0, Ah, Al, Bw, gate);
    gemm1_load(smb, 1, tid, 64, Ah, Al, Bw, gate);
    gemm1_load(smb, 2, tid, 128, Ah, Al, Bw, gate);

    // Mainloop: 4-stage rotation, always-commit, wait_group 2.
#pragma unroll
    for (int c = 0; c < 8; c++) {
        CP_WAIT2();
        __syncthreads();
        if (c + 3 < 8)
            gemm1_load(smb, (c + 3) & 3, tid, (c + 3) * 64, Ah, Al, Bw, gate);
        else
            CP_COMMIT();
        gemm1_compute(smb + (uint32_t)(c & 3) * G1_STAGE, wm, wn, L, acc, gate, gacc);
    }

    // Epilogue: bias + relu + fp16 hi/lo split -> g_h
    float bias[8][2];
#pragma unroll
    for (int nt = 0; nt < 8; nt++) {
        int gn = n0 + wn + nt * 8 + 2 * (L & 3);
        bias[nt][0] = b1[e * H1D + gn];
        bias[nt][1] = b1[e * H1D + gn + 1];
    }
#pragma unroll
    for (int mt = 0; mt < 2; mt++) {
        int gb = b0 + wm + mt * 16 + (L >> 2);
#pragma unroll
        for (int nt = 0; nt < 8; nt++) {
            int gn = n0 + wn + nt * 8 + 2 * (L & 3);
            float v00 = fmaxf(acc[mt][nt][0] + bias[nt][0], 0.f);
            float v01 = fmaxf(acc[mt][nt][1] + bias[nt][1], 0.f);
            float v10 = fmaxf(acc[mt][nt][2] + bias[nt][0], 0.f);
            float v11 = fmaxf(acc[mt][nt][3] + bias[nt][1], 0.f);
            __half h00, l00, h01, l01, h10, l10, h11, l11;
            split_f16(v00, h00, l00); split_f16(v01, h01, l01);
            split_f16(v10, h10, l10); split_f16(v11, h11, l11);
            size_t o0 = ((size_t)e * B_DIM + gb) * H1D + gn;
            size_t o1 = o0 + (size_t)8 * H1D;
            __half2 ph0; ph0.x = h00; ph0.y = h01;
            __half2 pl0; pl0.x = l00; pl0.y = l01;
            __half2 ph1; ph1.x = h10; ph1.y = h11;
            __half2 pl1; pl1.x = l10; pl1.y = l11;
            *(__half2*)(g_h_hi + o0) = ph0;
            *(__half2*)(g_h_lo + o0) = pl0;
            *(__half2*)(g_h_hi + o1) = ph1;
            *(__half2*)(g_h_lo + o1) = pl1;
        }
    }
    if (gate) {
#pragma unroll
        for (int mt = 0; mt < 2; mt++) {
            int gb = b0 + wm + mt * 16 + (L >> 2);
#pragma unroll
            for (int gt = 0; gt < 2; gt++) {
                int gc = gt * 8 + 2 * (L & 3);
                *(float2*)(g_glogits + (size_t)gb * 16 + gc) =
                    make_float2(gacc[mt][gt][0], gacc[mt][gt][1]);
                *(float2*)(g_glogits + (size_t)(gb + 8) * 16 + gc) =
                    make_float2(gacc[mt][gt][2], gacc[mt][gt][3]);
            }
        }
    }
}

// ---------------------------------------------------------------------------
// GEMM2 fused with softmax + gated combine.
// CTA: 64 b-rows x 128 h2-cols; loops over all 8 experts (32 K-chunks),
// accumulating out[t][b][:] += softmax_e(logits)[t][b][e] * relu(h@w2t + b2).
// Stage (32768 B): A_hi@0 (8K) | A_lo@8K (8K) | B@16K (16K)
// 4 stages + 4K gate cache.  8 warps = 2(m) x 4(n); warp tile 32x32.
// grid = B/64, 256 threads.
// ---------------------------------------------------------------------------
#define G2_STAGE 32768
#define G2_SMEM  (4 * G2_STAGE + 4096)

__device__ __forceinline__ void gemm2_load(uint32_t smb, int stage, int tid,
                                           int b0, int cg) {
    int e = cg >> 2, k0 = (cg & 3) * 64;
    const __half* Ah = g_h_hi + ((size_t)e * B_DIM + b0) * H1D;
    const __half* Al = g_h_lo + ((size_t)e * B_DIM + b0) * H1D;
    const __half* Bw = g_w2t + (size_t)e * H2D * H1D;
    uint32_t sb = smb + (uint32_t)stage * G2_STAGE;
#pragma unroll
    for (int t = 0; t < 8; t++) {
        int j = t * 256 + tid;
        const __half* p;
        uint32_t dst;
        int jj;
        if (j < 512)       { jj = j;        p = Ah; dst = 0u; }
        else if (j < 1024) { jj = j - 512;  p = Al; dst = 8192u; }
        else               { jj = j - 1024; p = Bw; dst = 16384u; }
        int row = jj >> 3, c8 = jj & 7;
        cp16(sb + dst + SWZ(row * 128 + c8 * 16),
             p + (size_t)row * H1D + k0 + c8 * 8);
    }
    CP_COMMIT();
}

__global__ void __launch_bounds__(256, 1)
gemm2_kernel(const float* __restrict__ b2, const float* __restrict__ bg,
             float* __restrict__ out) {
    extern __shared__ char sm[];
    uint32_t smb = smem_u32(sm);
    float* sgate = (float*)(sm + 4 * G2_STAGE);   // [2][64][8]
    const int b0 = blockIdx.x * 64;
    const int tid = threadIdx.x, L = tid & 31, w = tid >> 5;
    const int wm = (w >> 2) * 32, wn = (w & 3) * 32;

    // Prologue: prefetch chunks 0..2.
    gemm2_load(smb, 0, tid, b0, 0);
    gemm2_load(smb, 1, tid, b0, 1);
    gemm2_load(smb, 2, tid, b0, 2);

    // Fused softmax: threads 0..127 each handle one (row, task).
    if (tid < 128) {
        int r = tid >> 1, t = tid & 1;
        int b = b0 + r;
        float4 l0 = *(const float4*)(g_glogits + (size_t)b * 16 + t * 8);
        float4 l1 = *(const float4*)(g_glogits + (size_t)b * 16 + t * 8 + 4);
        float v[8] = {l0.x, l0.y, l0.z, l0.w, l1.x, l1.y, l1.z, l1.w};
        float m = -1e30f;
#pragma unroll
        for (int e2 = 0; e2 < 8; e2++) { v[e2] += bg[t * 8 + e2]; m = fmaxf(m, v[e2]); }
        float s = 0.f;
#pragma unroll
        for (int e2 = 0; e2 < 8; e2++) { v[e2] = expf(v[e2] - m); s += v[e2]; }
        float inv = 1.f / s;
#pragma unroll
        for (int e2 = 0; e2 < 8; e2++)
            sgate[(t * 64 + r) * 8 + e2] = v[e2] * inv;
    }

    float tacc[2][2][4][4];   // [task][mt][nt][quad]
#pragma unroll
    for (int t = 0; t < 2; t++)
#pragma unroll
        for (int mt = 0; mt < 2; mt++)
#pragma unroll
            for (int nt = 0; nt < 4; nt++)
#pragma unroll
                for (int q = 0; q < 4; q++) tacc[t][mt][nt][q] = 0.f;
    float eo[2][4][4];
#pragma unroll
    for (int mt = 0; mt < 2; mt++)
#pragma unroll
        for (int nt = 0; nt < 4; nt++)
#pragma unroll
            for (int q = 0; q < 4; q++) eo[mt][nt][q] = 0.f;

    for (int cg = 0; cg < 32; cg++) {
        CP_WAIT2();
        __syncthreads();
        if (cg + 3 < 32)
            gemm2_load(smb, (cg + 3) & 3, tid, b0, cg + 3);
        else
            CP_COMMIT();
        uint32_t sb = smb + (uint32_t)(cg & 3) * G2_STAGE;
#pragma unroll
        for (int ks = 0; ks < 4; ks++) {
            uint32_t afh[2][4], afl[2][4], bf[4][2];
#pragma unroll
            for (int mt = 0; mt < 2; mt++) {
                int row = wm + mt * 16 + (L & 15);
                int co = ks * 32 + ((L >> 4) & 1) * 16;
                ldsm4(afh[mt], sb + 0u    + SWZ(row * 128 + co));
                ldsm4(afl[mt], sb + 8192u + SWZ(row * 128 + co));
            }
#pragma unroll
            for (int np = 0; np < 2; np++) {
                int g = L >> 3;
                int n = wn + np * 16 + (g >> 1) * 8 + (L & 7);
                int co = ks * 32 + (g & 1) * 16;
                uint32_t r[4];
                ldsm4(r, sb + 16384u + SWZ(n * 128 + co));
                bf[np * 2][0] = r[0]; bf[np * 2][1] = r[1];
                bf[np * 2 + 1][0] = r[2]; bf[np * 2 + 1][1] = r[3];
            }
#pragma unroll
            for (int mt = 0; mt < 2; mt++)
#pragma unroll
                for (int nt = 0; nt < 4; nt++) {
                    mma16816(eo[mt][nt], afh[mt], bf[nt]);
                    mma16816(eo[mt][nt], afl[mt], bf[nt]);
                }
        }

        if ((cg & 3) == 3) {
            // Expert complete: relu+bias, gate-weight, fold into towers.
            int e = cg >> 2;
#pragma unroll
            for (int mt = 0; mt < 2; mt++) {
                int r1 = wm + mt * 16 + (L >> 2);
                int r2 = r1 + 8;
                float g0a = sgate[(0 * 64 + r1) * 8 + e];
                float g0b = sgate[(0 * 64 + r2) * 8 + e];
                float g1a = sgate[(1 * 64 + r1) * 8 + e];
                float g1b = sgate[(1 * 64 + r2) * 8 + e];
#pragma unroll
                for (int nt = 0; nt < 4; nt++) {
                    int gc = wn + nt * 8 + 2 * (L & 3);
                    float bz0 = b2[e * H2D + gc];
                    float bz1 = b2[e * H2D + gc + 1];
                    float v00 = fmaxf(eo[mt][nt][0] + bz0, 0.f);
                    float v01 = fmaxf(eo[mt][nt][1] + bz1, 0.f);
                    float v10 = fmaxf(eo[mt][nt][2] + bz0, 0.f);
                    float v11 = fmaxf(eo[mt][nt][3] + bz1, 0.f);
                    tacc[0][mt][nt][0] += g0a * v00; tacc[0][mt][nt][1] += g0a * v01;
                    tacc[0][mt][nt][2] += g0b * v10; tacc[0][mt][nt][3] += g0b * v11;
                    tacc[1][mt][nt][0] += g1a * v00; tacc[1][mt][nt][1] += g1a * v01;
                    tacc[1][mt][nt][2] += g1b * v10; tacc[1][mt][nt][3] += g1b * v11;
                    eo[mt][nt][0] = 0.f; eo[mt][nt][1] = 0.f;
                    eo[mt][nt][2] = 0.f; eo[mt][nt][3] = 0.f;
                }
            }
        }
    }

    // Write towers: out[t][b][h2]
#pragma unroll
    for (int t = 0; t < 2; t++)
#pragma unroll
        for (int mt = 0; mt < 2; mt++) {
            int r1 = b0 + wm + mt * 16 + (L >> 2);
#pragma unroll
            for (int nt = 0; nt < 4; nt++) {
                int gc = wn + nt * 8 + 2 * (L & 3);
                *(float2*)(out + ((size_t)t * B_DIM + r1) * H2D + gc) =
                    make_float2(tacc[t][mt][nt][0], tacc[t][mt][nt][1]);
                *(float2*)(out + ((size_t)t * B_DIM + r1 + 8) * H2D + gc) =
                    make_float2(tacc[t][mt][nt][2], tacc[t][mt][nt][3]);
            }
        }
}

// ---------------------------------------------------------------------------
// Prep kernels
// ---------------------------------------------------------------------------
__global__ void split_x_kernel(const float* __restrict__ x) {
    size_t idx = (size_t)blockIdx.x * blockDim.x + threadIdx.x;
    float4 v = ((const float4*)x)[idx];
    __half h0, l0, h1, l1, h2, l2, h3, l3;
    split_f16(v.x, h0, l0); split_f16(v.y, h1, l1);
    split_f16(v.z, h2, l2); split_f16(v.w, h3, l3);
    __half2 ph0, ph1, pl0, pl1;
    ph0.x = h0; ph0.y = h1; ph1.x = h2; ph1.y = h3;
    pl0.x = l0; pl0.y = l1; pl1.x = l2; pl1.y = l3;
    ((__half2*)g_x_hi)[idx * 2 + 0] = ph0;
    ((__half2*)g_x_hi)[idx * 2 + 1] = ph1;
    ((__half2*)g_x_lo)[idx * 2 + 0] = pl0;
    ((__half2*)g_x_lo)[idx * 2 + 1] = pl1;
}

__global__ void prep_w1_kernel(const float* __restrict__ W1) {
    __shared__ float t[32][33];
    int e = blockIdx.z, h0 = blockIdx.x * 32, i0 = blockIdx.y * 32;
    int tx = threadIdx.x, ty = threadIdx.y;
    const float* src = W1 + (size_t)e * I_DIM * H1D;
#pragma unroll
    for (int j = 0; j < 4; j++)
        t[ty + j * 8][tx] = src[(size_t)(i0 + ty + j * 8) * H1D + h0 + tx];
    __syncthreads();
#pragma unroll
    for (int j = 0; j < 4; j++) {
        float v = t[tx][ty + j * 8];
        size_t o = ((size_t)e * H1D + h0 + ty + j * 8) * I_DIM + i0 + tx;
        g_w1t[o] = __float2half_rn(v);
    }
}

__global__ void prep_w2_kernel(const float* __restrict__ W2) {
    __shared__ float t[32][33];
    int e = blockIdx.z, h2_0 = blockIdx.x * 32, h1_0 = blockIdx.y * 32;
    int tx = threadIdx.x, ty = threadIdx.y;
    const float* src = W2 + (size_t)e * H1D * H2D;
#pragma unroll
    for (int j = 0; j < 4; j++)
        t[ty + j * 8][tx] = src[(size_t)(h1_0 + ty + j * 8) * H2D + h2_0 + tx];
    __syncthreads();
#pragma unroll
    for (int j = 0; j < 4; j++) {
        float v = t[tx][ty + j * 8];
        size_t o = ((size_t)e * H2D + h2_0 + ty + j * 8) * H1D + h1_0 + tx;
        g_w2t[o] = __float2half_rn(v);
    }
}

// Wg [T][I][E] -> wgt [t*8+e][I] fp16.  8192 elems.
__global__ void prep_wg_kernel(const float* __restrict__ Wg) {
    int idx = blockIdx.x * blockDim.x + threadIdx.x;
    if (idx >= 16 * I_DIM) return;
    int i = idx & (I_DIM - 1), r = idx >> 9;
    int t = r >> 3, e = r & 7;
    float v = Wg[((size_t)t * I_DIM + i) * E_DIM + e];
    g_wgt[(size_t)r * I_DIM + i] = __float2half_rn(v);
}

// ---------------------------------------------------------------------------
extern "C" void kernel_launch(void* const* d_in, const int* in_sizes, int n_in,
                              void* d_out, int out_size) {
    const float* x  = (const float*)d_in[0];
    const float* W1 = (const float*)d_in[1];
    const float* b1 = (const float*)d_in[2];
    const float* W2 = (const float*)d_in[3];
    const float* b2 = (const float*)d_in[4];
    const float* Wg = (const float*)d_in[5];
    const float* bg = (const float*)d_in[6];
    float* out = (float*)d_out;

    cudaFuncSetAttribute(gemm1_kernel, cudaFuncAttributeMaxDynamicSharedMemorySize, G1_SMEM);
    cudaFuncSetAttribute(gemm2_kernel, cudaFuncAttributeMaxDynamicSharedMemorySize, G2_SMEM);

    split_x_kernel<<<(B_DIM * I_DIM / 4) / 256, 256>>>(x);
    prep_w1_kernel<<<dim3(H1D / 32, I_DIM / 32, E_DIM), dim3(32, 8)>>>(W1);
    prep_w2_kernel<<<dim3(H2D / 32, H1D / 32, E_DIM), dim3(32, 8)>>>(W2);
    prep_wg_kernel<<<(16 * I_DIM) / 256, 256>>>(Wg);

    gemm1_kernel<<<dim3(B_DIM / 128, H1D / 128, E_DIM), 256, G1_SMEM>>>(b1);
    gemm2_kernel<<<B_DIM / 64, 256, G2_SMEM>>>(b2, bg, out);
}

// round 16
// speedup vs baseline: 7.2023x; 1.6309x over previous
#include <cuda_runtime.h>
#include <cuda_fp16.h>
#include <cstdint>

// Problem constants
#define B_DIM 16384
#define I_DIM 512
#define H1D   256
#define H2D   128
#define E_DIM 8
#define T_DIM 2

// ---------------------------------------------------------------------------
// Device globals — single-fp16 numerics for both operands (1 MMA / product).
// Calibration: weights-only fp16 rounding measured rel_err 2.3e-4 (R15);
// adding activation rounding predicts ~3-5e-4 vs the 1e-3 threshold.
// ---------------------------------------------------------------------------
__device__ __half g_x16[(size_t)B_DIM * I_DIM];
__device__ __half g_w1t[(size_t)E_DIM * H1D * I_DIM];   // [E][H1][I]
__device__ __half g_w2t[(size_t)E_DIM * H2D * H1D];     // [E][H2][H1]
__device__ __half g_wgt[16 * I_DIM];                    // [t*8+e][I]
__device__ __half g_h16[(size_t)E_DIM * B_DIM * H1D];   // [E][B][H1]
__device__ float  g_glogits[(size_t)B_DIM * 16];        // [B][t*8+e]

// ---------------------------------------------------------------------------
// Helpers (sm_80+ only — environment compiles virtual compute_103, which
// rejects all tcgen05/sm_103a-suffix instructions)
// ---------------------------------------------------------------------------
__device__ __forceinline__ uint32_t smem_u32(const void* p) {
    uint32_t a;
    asm("{ .reg .u64 t; cvta.to.shared.u64 t, %1; cvt.u32.u64 %0, t; }"
        : "=r"(a) : "l"(p));
    return a;
}

// 128B-period XOR swizzle
#define SWZ(o) ((uint32_t)(o) ^ ((((uint32_t)(o)) >> 3) & 0x70u))

__device__ __forceinline__ void cp16(uint32_t s, const void* g) {
    asm volatile("cp.async.cg.shared.global [%0], [%1], 16;"
                 :: "r"(s), "l"(__cvta_generic_to_global(g)));
}
#define CP_COMMIT() asm volatile("cp.async.commit_group;" ::: "memory")
#define CP_WAIT2()  asm volatile("cp.async.wait_group 2;" ::: "memory")

__device__ __forceinline__ void ldsm4(uint32_t* r, uint32_t addr) {
    asm volatile("ldmatrix.sync.aligned.m8n8.x4.shared.b16 {%0,%1,%2,%3}, [%4];"
                 : "=r"(r[0]), "=r"(r[1]), "=r"(r[2]), "=r"(r[3]) : "r"(addr));
}

__device__ __forceinline__ void mma16816(float* d, const uint32_t* a, const uint32_t* b) {
    asm volatile("mma.sync.aligned.m16n8k16.row.col.f32.f16.f16.f32 "
                 "{%0,%1,%2,%3}, {%4,%5,%6,%7}, {%8,%9}, {%0,%1,%2,%3};"
                 : "+f"(d[0]), "+f"(d[1]), "+f"(d[2]), "+f"(d[3])
                 : "r"(a[0]), "r"(a[1]), "r"(a[2]), "r"(a[3]), "r"(b[0]), "r"(b[1]));
}

// ---------------------------------------------------------------------------
// GEMM1 stage layout (34816 B):  A @0 (16K) | B @16K (16K) | Wg @32K (2K)
// Tiles: A 128x64 fp16, B 128x64, Wg 16x64; pitch 128B, swizzled.
// 4 stages, always-commit, wait_group 2 (3-chunk prefetch depth).
// Warp grid: 8 warps = 4(m) x 2(n); warp tile 32x64 = 2x8 m16n8 tiles.
// ---------------------------------------------------------------------------
#define G1_STAGE 34816
#define G1_SMEM  (4 * G1_STAGE)

__device__ __forceinline__ void gemm1_compute(uint32_t sb, int wm, int wn, int L,
                                              float acc[2][8][4],
                                              bool gate, float gacc[2][2][4]) {
#pragma unroll
    for (int ks = 0; ks < 4; ks++) {
        uint32_t af[2][4], bf[8][2];
#pragma unroll
        for (int mt = 0; mt < 2; mt++) {
            int row = wm + mt * 16 + (L & 15);
            int co = ks * 32 + ((L >> 4) & 1) * 16;
            ldsm4(af[mt], sb + 0u + SWZ(row * 128 + co));
        }
#pragma unroll
        for (int np = 0; np < 4; np++) {
            int g = L >> 3;
            int n = wn + np * 16 + (g >> 1) * 8 + (L & 7);
            int co = ks * 32 + (g & 1) * 16;
            uint32_t r[4];
            ldsm4(r, sb + 16384u + SWZ(n * 128 + co));
            bf[np * 2][0] = r[0]; bf[np * 2][1] = r[1];
            bf[np * 2 + 1][0] = r[2]; bf[np * 2 + 1][1] = r[3];
        }
#pragma unroll
        for (int mt = 0; mt < 2; mt++)
#pragma unroll
            for (int nt = 0; nt < 8; nt++)
                mma16816(acc[mt][nt], af[mt], bf[nt]);
        if (gate) {
            int g = L >> 3;
            int n = (g >> 1) * 8 + (L & 7);
            int co = ks * 32 + (g & 1) * 16;
            uint32_t rg[4];
            ldsm4(rg, sb + 32768u + SWZ(n * 128 + co));
            uint32_t gb[2][2] = {{rg[0], rg[1]}, {rg[2], rg[3]}};
#pragma unroll
            for (int mt = 0; mt < 2; mt++)
#pragma unroll
                for (int gt = 0; gt < 2; gt++)
                    mma16816(gacc[mt][gt], af[mt], gb[gt]);
        }
    }
}

__device__ __forceinline__ void gemm1_load(uint32_t smb, int stage, int tid, int k0,
                                           const __half* Aw, const __half* Bw,
                                           bool gate) {
    uint32_t sb = smb + (uint32_t)stage * G1_STAGE;
#pragma unroll
    for (int t = 0; t < 8; t++) {
        const int mat = t >> 2;   // 0: A, 1: B
        const __half* p = (mat == 0) ? Aw : Bw;
        int j = (t & 3) * 256 + tid;
        int row = j >> 3, c8 = j & 7;
        cp16(sb + (uint32_t)mat * 16384u + SWZ(row * 128 + c8 * 16),
             p + (size_t)row * I_DIM + k0 + c8 * 8);
    }
    if (gate && tid < 128) {
        int row = tid >> 3, c8 = tid & 7;
        cp16(sb + 32768u + SWZ(row * 128 + c8 * 16),
             g_wgt + (size_t)row * I_DIM + k0 + c8 * 8);
    }
    CP_COMMIT();
}

// ---------------------------------------------------------------------------
// GEMM1: C[b][h1] = x[b][:] . w1t[h1][:]  (per expert), +b1, relu -> g_h16.
// Gate CTAs (n0==0,e==0) also emit x@Wg^T logits.
// grid = (B/128, H1/128, E), 256 threads.
// ---------------------------------------------------------------------------
__global__ void __launch_bounds__(256, 1)
gemm1_kernel(const float* __restrict__ b1) {
    extern __shared__ char sm[];
    uint32_t smb = smem_u32(sm);
    const int e = blockIdx.z, b0 = blockIdx.x * 128, n0 = blockIdx.y * 128;
    const int tid = threadIdx.x, L = tid & 31, w = tid >> 5;
    const int wm = (w >> 1) * 32, wn = (w & 1) * 64;
    const bool gate = (blockIdx.y == 0) && (blockIdx.z == 0);

    const __half* Aw = g_x16 + (size_t)b0 * I_DIM;
    const __half* Bw = g_w1t + ((size_t)e * H1D + n0) * I_DIM;

    float acc[2][8][4];
    float gacc[2][2][4];
#pragma unroll
    for (int mt = 0; mt < 2; mt++) {
#pragma unroll
        for (int nt = 0; nt < 8; nt++)
#pragma unroll
            for (int q = 0; q < 4; q++) acc[mt][nt][q] = 0.f;
#pragma unroll
        for (int gt = 0; gt < 2; gt++)
#pragma unroll
            for (int q = 0; q < 4; q++) gacc[mt][gt][q] = 0.f;
    }

    // Prologue: prefetch chunks 0..2 into stages 0..2.
    gemm1_load(smb, 0, tid, 0, Aw, Bw, gate);
    gemm1_load(smb, 1, tid, 64, Aw, Bw, gate);
    gemm1_load(smb, 2, tid, 128, Aw, Bw, gate);

    // Mainloop: 4-stage rotation, always-commit, wait_group 2.
#pragma unroll
    for (int c = 0; c < 8; c++) {
        CP_WAIT2();
        __syncthreads();
        if (c + 3 < 8)
            gemm1_load(smb, (c + 3) & 3, tid, (c + 3) * 64, Aw, Bw, gate);
        else
            CP_COMMIT();
        gemm1_compute(smb + (uint32_t)(c & 3) * G1_STAGE, wm, wn, L, acc, gate, gacc);
    }

    // Epilogue: bias + relu -> fp16 h
    float bias[8][2];
#pragma unroll
    for (int nt = 0; nt < 8; nt++) {
        int gn = n0 + wn + nt * 8 + 2 * (L & 3);
        bias[nt][0] = b1[e * H1D + gn];
        bias[nt][1] = b1[e * H1D + gn + 1];
    }
#pragma unroll
    for (int mt = 0; mt < 2; mt++) {
        int gb = b0 + wm + mt * 16 + (L >> 2);
#pragma unroll
        for (int nt = 0; nt < 8; nt++) {
            int gn = n0 + wn + nt * 8 + 2 * (L & 3);
            float v00 = fmaxf(acc[mt][nt][0] + bias[nt][0], 0.f);
            float v01 = fmaxf(acc[mt][nt][1] + bias[nt][1], 0.f);
            float v10 = fmaxf(acc[mt][nt][2] + bias[nt][0], 0.f);
            float v11 = fmaxf(acc[mt][nt][3] + bias[nt][1], 0.f);
            size_t o0 = ((size_t)e * B_DIM + gb) * H1D + gn;
            size_t o1 = o0 + (size_t)8 * H1D;
            __half2 p0; p0.x = __float2half_rn(v00); p0.y = __float2half_rn(v01);
            __half2 p1; p1.x = __float2half_rn(v10); p1.y = __float2half_rn(v11);
            *(__half2*)(g_h16 + o0) = p0;
            *(__half2*)(g_h16 + o1) = p1;
        }
    }
    if (gate) {
#pragma unroll
        for (int mt = 0; mt < 2; mt++) {
            int gb = b0 + wm + mt * 16 + (L >> 2);
#pragma unroll
            for (int gt = 0; gt < 2; gt++) {
                int gc = gt * 8 + 2 * (L & 3);
                *(float2*)(g_glogits + (size_t)gb * 16 + gc) =
                    make_float2(gacc[mt][gt][0], gacc[mt][gt][1]);
                *(float2*)(g_glogits + (size_t)(gb + 8) * 16 + gc) =
                    make_float2(gacc[mt][gt][2], gacc[mt][gt][3]);
            }
        }
    }
}

// ---------------------------------------------------------------------------
// GEMM2 fused with softmax + gated combine.
// CTA: 64 b-rows x 128 h2-cols; loops over all 8 experts (32 K-chunks),
// accumulating out[t][b][:] += softmax_e(logits)[t][b][e] * relu(h@w2t + b2).
// Stage (24576 B): A @0 (8K) | B @8K (16K).  4 stages + 4K gate cache.
// 8 warps = 2(m) x 4(n); warp tile 32x32.  grid = B/64, 256 threads.
// ---------------------------------------------------------------------------
#define G2_STAGE 24576
#define G2_SMEM  (4 * G2_STAGE + 4096)

__device__ __forceinline__ void gemm2_load(uint32_t smb, int stage, int tid,
                                           int b0, int cg) {
    int e = cg >> 2, k0 = (cg & 3) * 64;
    const __half* Aw = g_h16 + ((size_t)e * B_DIM + b0) * H1D;
    const __half* Bw = g_w2t + (size_t)e * H2D * H1D;
    uint32_t sb = smb + (uint32_t)stage * G2_STAGE;
#pragma unroll
    for (int t = 0; t < 6; t++) {
        int j = t * 256 + tid;
        const __half* p;
        uint32_t dst;
        int jj;
        if (j < 512) { jj = j;       p = Aw; dst = 0u; }
        else         { jj = j - 512; p = Bw; dst = 8192u; }
        int row = jj >> 3, c8 = jj & 7;
        cp16(sb + dst + SWZ(row * 128 + c8 * 16),
             p + (size_t)row * H1D + k0 + c8 * 8);
    }
    CP_COMMIT();
}

__global__ void __launch_bounds__(256, 1)
gemm2_kernel(const float* __restrict__ b2, const float* __restrict__ bg,
             float* __restrict__ out) {
    extern __shared__ char sm[];
    uint32_t smb = smem_u32(sm);
    float* sgate = (float*)(sm + 4 * G2_STAGE);   // [2][64][8]
    const int b0 = blockIdx.x * 64;
    const int tid = threadIdx.x, L = tid & 31, w = tid >> 5;
    const int wm = (w >> 2) * 32, wn = (w & 3) * 32;

    // Prologue: prefetch chunks 0..2.
    gemm2_load(smb, 0, tid, b0, 0);
    gemm2_load(smb, 1, tid, b0, 1);
    gemm2_load(smb, 2, tid, b0, 2);

    // Fused softmax: threads 0..127 each handle one (row, task).
    if (tid < 128) {
        int r = tid >> 1, t = tid & 1;
        int b = b0 + r;
        float4 l0 = *(const float4*)(g_glogits + (size_t)b * 16 + t * 8);
        float4 l1 = *(const float4*)(g_glogits + (size_t)b * 16 + t * 8 + 4);
        float v[8] = {l0.x, l0.y, l0.z, l0.w, l1.x, l1.y, l1.z, l1.w};
        float m = -1e30f;
#pragma unroll
        for (int e2 = 0; e2 < 8; e2++) { v[e2] += bg[t * 8 + e2]; m = fmaxf(m, v[e2]); }
        float s = 0.f;
#pragma unroll
        for (int e2 = 0; e2 < 8; e2++) { v[e2] = expf(v[e2] - m); s += v[e2]; }
        float inv = 1.f / s;
#pragma unroll
        for (int e2 = 0; e2 < 8; e2++)
            sgate[(t * 64 + r) * 8 + e2] = v[e2] * inv;
    }

    float tacc[2][2][4][4];   // [task][mt][nt][quad]
#pragma unroll
    for (int t = 0; t < 2; t++)
#pragma unroll
        for (int mt = 0; mt < 2; mt++)
#pragma unroll
            for (int nt = 0; nt < 4; nt++)
#pragma unroll
                for (int q = 0; q < 4; q++) tacc[t][mt][nt][q] = 0.f;
    float eo[2][4][4];
#pragma unroll
    for (int mt = 0; mt < 2; mt++)
#pragma unroll
        for (int nt = 0; nt < 4; nt++)
#pragma unroll
            for (int q = 0; q < 4; q++) eo[mt][nt][q] = 0.f;

    for (int cg = 0; cg < 32; cg++) {
        CP_WAIT2();
        __syncthreads();
        if (cg + 3 < 32)
            gemm2_load(smb, (cg + 3) & 3, tid, b0, cg + 3);
        else
            CP_COMMIT();
        uint32_t sb = smb + (uint32_t)(cg & 3) * G2_STAGE;
#pragma unroll
        for (int ks = 0; ks < 4; ks++) {
            uint32_t af[2][4], bf[4][2];
#pragma unroll
            for (int mt = 0; mt < 2; mt++) {
                int row = wm + mt * 16 + (L & 15);
                int co = ks * 32 + ((L >> 4) & 1) * 16;
                ldsm4(af[mt], sb + 0u + SWZ(row * 128 + co));
            }
#pragma unroll
            for (int np = 0; np < 2; np++) {
                int g = L >> 3;
                int n = wn + np * 16 + (g >> 1) * 8 + (L & 7);
                int co = ks * 32 + (g & 1) * 16;
                uint32_t r[4];
                ldsm4(r, sb + 8192u + SWZ(n * 128 + co));
                bf[np * 2][0] = r[0]; bf[np * 2][1] = r[1];
                bf[np * 2 + 1][0] = r[2]; bf[np * 2 + 1][1] = r[3];
            }
#pragma unroll
            for (int mt = 0; mt < 2; mt++)
#pragma unroll
                for (int nt = 0; nt < 4; nt++)
                    mma16816(eo[mt][nt], af[mt], bf[nt]);
        }

        if ((cg & 3) == 3) {
            // Expert complete: relu+bias, gate-weight, fold into towers.
            int e = cg >> 2;
#pragma unroll
            for (int mt = 0; mt < 2; mt++) {
                int r1 = wm + mt * 16 + (L >> 2);
                int r2 = r1 + 8;
                float g0a = sgate[(0 * 64 + r1) * 8 + e];
                float g0b = sgate[(0 * 64 + r2) * 8 + e];
                float g1a = sgate[(1 * 64 + r1) * 8 + e];
                float g1b = sgate[(1 * 64 + r2) * 8 + e];
#pragma unroll
                for (int nt = 0; nt < 4; nt++) {
                    int gc = wn + nt * 8 + 2 * (L & 3);
                    float bz0 = b2[e * H2D + gc];
                    float bz1 = b2[e * H2D + gc + 1];
                    float v00 = fmaxf(eo[mt][nt][0] + bz0, 0.f);
                    float v01 = fmaxf(eo[mt][nt][1] + bz1, 0.f);
                    float v10 = fmaxf(eo[mt][nt][2] + bz0, 0.f);
                    float v11 = fmaxf(eo[mt][nt][3] + bz1, 0.f);
                    tacc[0][mt][nt][0] += g0a * v00; tacc[0][mt][nt][1] += g0a * v01;
                    tacc[0][mt][nt][2] += g0b * v10; tacc[0][mt][nt][3] += g0b * v11;
                    tacc[1][mt][nt][0] += g1a * v00; tacc[1][mt][nt][1] += g1a * v01;
                    tacc[1][mt][nt][2] += g1b * v10; tacc[1][mt][nt][3] += g1b * v11;
                    eo[mt][nt][0] = 0.f; eo[mt][nt][1] = 0.f;
                    eo[mt][nt][2] = 0.f; eo[mt][nt][3] = 0.f;
                }
            }
        }
    }

    // Write towers: out[t][b][h2]
#pragma unroll
    for (int t = 0; t < 2; t++)
#pragma unroll
        for (int mt = 0; mt < 2; mt++) {
            int r1 = b0 + wm + mt * 16 + (L >> 2);
#pragma unroll
            for (int nt = 0; nt < 4; nt++) {
                int gc = wn + nt * 8 + 2 * (L & 3);
                *(float2*)(out + ((size_t)t * B_DIM + r1) * H2D + gc) =
                    make_float2(tacc[t][mt][nt][0], tacc[t][mt][nt][1]);
                *(float2*)(out + ((size_t)t * B_DIM + r1 + 8) * H2D + gc) =
                    make_float2(tacc[t][mt][nt][2], tacc[t][mt][nt][3]);
            }
        }
}

// ---------------------------------------------------------------------------
// Prep kernels
// ---------------------------------------------------------------------------
__global__ void conv_x_kernel(const float* __restrict__ x) {
    size_t idx = (size_t)blockIdx.x * blockDim.x + threadIdx.x;
    float4 v = ((const float4*)x)[idx];
    __half2 p0, p1;
    p0.x = __float2half_rn(v.x); p0.y = __float2half_rn(v.y);
    p1.x = __float2half_rn(v.z); p1.y = __float2half_rn(v.w);
    ((__half2*)g_x16)[idx * 2 + 0] = p0;
    ((__half2*)g_x16)[idx * 2 + 1] = p1;
}

__global__ void prep_w1_kernel(const float* __restrict__ W1) {
    __shared__ float t[32][33];
    int e = blockIdx.z, h0 = blockIdx.x * 32, i0 = blockIdx.y * 32;
    int tx = threadIdx.x, ty = threadIdx.y;
    const float* src = W1 + (size_t)e * I_DIM * H1D;
#pragma unroll
    for (int j = 0; j < 4; j++)
        t[ty + j * 8][tx] = src[(size_t)(i0 + ty + j * 8) * H1D + h0 + tx];
    __syncthreads();
#pragma unroll
    for (int j = 0; j < 4; j++) {
        float v = t[tx][ty + j * 8];
        size_t o = ((size_t)e * H1D + h0 + ty + j * 8) * I_DIM + i0 + tx;
        g_w1t[o] = __float2half_rn(v);
    }
}

__global__ void prep_w2_kernel(const float* __restrict__ W2) {
    __shared__ float t[32][33];
    int e = blockIdx.z, h2_0 = blockIdx.x * 32, h1_0 = blockIdx.y * 32;
    int tx = threadIdx.x, ty = threadIdx.y;
    const float* src = W2 + (size_t)e * H1D * H2D;
#pragma unroll
    for (int j = 0; j < 4; j++)
        t[ty + j * 8][tx] = src[(size_t)(h1_0 + ty + j * 8) * H2D + h2_0 + tx];
    __syncthreads();
#pragma unroll
    for (int j = 0; j < 4; j++) {
        float v = t[tx][ty + j * 8];
        size_t o = ((size_t)e * H2D + h2_0 + ty + j * 8) * H1D + h1_0 + tx;
        g_w2t[o] = __float2half_rn(v);
    }
}

// Wg [T][I][E] -> wgt [t*8+e][I] fp16.  8192 elems.
__global__ void prep_wg_kernel(const float* __restrict__ Wg) {
    int idx = blockIdx.x * blockDim.x + threadIdx.x;
    if (idx >= 16 * I_DIM) return;
    int i = idx & (I_DIM - 1), r = idx >> 9;
    int t = r >> 3, e = r & 7;
    float v = Wg[((size_t)t * I_DIM + i) * E_DIM + e];
    g_wgt[(size_t)r * I_DIM + i] = __float2half_rn(v);
}

// ---------------------------------------------------------------------------
extern "C" void kernel_launch(void* const* d_in, const int* in_sizes, int n_in,
                              void* d_out, int out_size) {
    const float* x  = (const float*)d_in[0];
    const float* W1 = (const float*)d_in[1];
    const float* b1 = (const float*)d_in[2];
    const float* W2 = (const float*)d_in[3];
    const float* b2 = (const float*)d_in[4];
    const float* Wg = (const float*)d_in[5];
    const float* bg = (const float*)d_in[6];
    float* out = (float*)d_out;

    cudaFuncSetAttribute(gemm1_kernel, cudaFuncAttributeMaxDynamicSharedMemorySize, G1_SMEM);
    cudaFuncSetAttribute(gemm2_kernel, cudaFuncAttributeMaxDynamicSharedMemorySize, G2_SMEM);

    conv_x_kernel<<<(B_DIM * I_DIM / 4) / 256, 256>>>(x);
    prep_w1_kernel<<<dim3(H1D / 32, I_DIM / 32, E_DIM), dim3(32, 8)>>>(W1);
    prep_w2_kernel<<<dim3(H2D / 32, H1D / 32, E_DIM), dim3(32, 8)>>>(W2);
    prep_wg_kernel<<<(16 * I_DIM) / 256, 256>>>(Wg);

    gemm1_kernel<<<dim3(B_DIM / 128, H1D / 128, E_DIM), 256, G1_SMEM>>>(b1);
    gemm2_kernel<<<B_DIM / 64, 256, G2_SMEM>>>(b2, bg, out);
}